// round 3
// baseline (speedup 1.0000x reference)
#include <cuda_runtime.h>
#include <cstddef>

constexpr int NN   = 10000;
constexpr int EE   = 320000;
constexpr int DIN  = 512;
constexpr int DOUT = 256;

// Scratch (no allocations allowed) — __device__ globals.
__device__ float g_h[(size_t)NN * DOUT];
__device__ float g_mean[(size_t)NN * DOUT];
__device__ float g_invdeg[NN];
__device__ int   g_degi[NN];
__device__ int   g_off[NN];
__device__ int   g_cur[NN];
__device__ int   g_src[EE];
__device__ int   g_dst[EE];
__device__ int   g_csr[EE];
__device__ int   g_is64;

// ---------------------------------------------------------------------------
// Edge-index dtype detection (int64 vs int32): odd 32-bit words of the first
// 1024 entries are all zero iff data is int64 with node ids < 2^31.
// ---------------------------------------------------------------------------
__global__ void detect_kernel(const int* __restrict__ raw) {
    int nz = 0;
    for (int i = threadIdx.x; i < 1024; i += blockDim.x)
        nz |= (raw[2 * i + 1] != 0);
    nz = __syncthreads_or(nz);
    if (threadIdx.x == 0) g_is64 = nz ? 0 : 1;
}

__global__ void decode_kernel(const int* __restrict__ raw,
                              int* __restrict__ src, int* __restrict__ dst) {
    int e = blockIdx.x * blockDim.x + threadIdx.x;
    if (e >= EE) return;
    if (g_is64) {
        src[e] = raw[2 * e];
        dst[e] = raw[2 * (EE + e)];
    } else {
        src[e] = raw[e];
        dst[e] = raw[EE + e];
    }
}

__global__ void zero_degi_kernel(int* __restrict__ degi) {
    int i = blockIdx.x * blockDim.x + threadIdx.x;
    if (i < NN) degi[i] = 0;
}

__global__ void degi_kernel(const int* __restrict__ dst, int* __restrict__ degi) {
    int e = blockIdx.x * blockDim.x + threadIdx.x;
    if (e < EE) atomicAdd(&degi[dst[e]], 1);
}

// ---------------------------------------------------------------------------
// Single-block exclusive scan over degrees -> CSR offsets + fill cursors +
// invdeg. 256 threads x 40 nodes each.
// ---------------------------------------------------------------------------
__global__ void scan_kernel(const int* __restrict__ degi, int* __restrict__ off,
                            int* __restrict__ cur, float* __restrict__ invdeg) {
    __shared__ int part[256];
    const int t = threadIdx.x;
    const int CH = (NN + 255) / 256;   // 40
    const int s0 = t * CH;
    int sum = 0;
    for (int j = 0; j < CH; j++) {
        int i = s0 + j;
        if (i < NN) sum += degi[i];
    }
    part[t] = sum;
    __syncthreads();
    for (int d = 1; d < 256; d <<= 1) {
        int v = (t >= d) ? part[t - d] : 0;
        __syncthreads();
        part[t] += v;
        __syncthreads();
    }
    int run = (t > 0) ? part[t - 1] : 0;
    for (int j = 0; j < CH; j++) {
        int i = s0 + j;
        if (i < NN) {
            off[i] = run;
            cur[i] = run;
            int d = degi[i];
            run += d;
            invdeg[i] = 1.0f / fmaxf((float)d, 1.0f);
        }
    }
}

__global__ void fill_kernel(const int* __restrict__ src, const int* __restrict__ dst,
                            int* __restrict__ cur, int* __restrict__ csr) {
    int e = blockIdx.x * blockDim.x + threadIdx.x;
    if (e < EE) {
        int p = atomicAdd(&cur[dst[e]], 1);
        csr[p] = src[e];
    }
}

// ---------------------------------------------------------------------------
// CSR gather aggregation: mean[i] = (1/deg_i) * sum_{e in in(i)} h[src(e)].
// One 64-thread block per node, one float4 column chunk per thread.
// Pure gather (L2-resident), no atomics, writes only 10 MB.
// ---------------------------------------------------------------------------
__global__ void gather_kernel(const float* __restrict__ h,
                              const int* __restrict__ csr,
                              const int* __restrict__ off,
                              const int* __restrict__ degi,
                              const float* __restrict__ invdeg,
                              float* __restrict__ mean) {
    const int node = blockIdx.x;
    const int t = threadIdx.x;               // 0..63
    const int base = off[node];
    const int n = degi[node];
    const float4* hp = (const float4*)h;
    float4 acc = make_float4(0.f, 0.f, 0.f, 0.f);
    int e = 0;
    for (; e + 4 <= n; e += 4) {
        int s0 = csr[base + e + 0];
        int s1 = csr[base + e + 1];
        int s2 = csr[base + e + 2];
        int s3 = csr[base + e + 3];
        float4 v0 = hp[(size_t)s0 * 64 + t];
        float4 v1 = hp[(size_t)s1 * 64 + t];
        float4 v2 = hp[(size_t)s2 * 64 + t];
        float4 v3 = hp[(size_t)s3 * 64 + t];
        acc.x += (v0.x + v1.x) + (v2.x + v3.x);
        acc.y += (v0.y + v1.y) + (v2.y + v3.y);
        acc.z += (v0.z + v1.z) + (v2.z + v3.z);
        acc.w += (v0.w + v1.w) + (v2.w + v3.w);
    }
    for (; e < n; e++) {
        int s = csr[base + e];
        float4 v = hp[(size_t)s * 64 + t];
        acc.x += v.x; acc.y += v.y; acc.z += v.z; acc.w += v.w;
    }
    const float s = invdeg[node];
    float4 o = make_float4(acc.x * s, acc.y * s, acc.z * s, acc.w * s);
    ((float4*)mean)[(size_t)node * 64 + t] = o;
}

// ---------------------------------------------------------------------------
// f32x2 fused dual-GEMM: C = op( A1@W1 + A2@W2 + bias ) [+ res]
// BM=128, BN=64, BK=16, 256 threads. Per-thread 8x4 micro-tile held as
// 4x4 f32x2 accumulators (pairs along M). B stored pre-duplicated in smem so
// the f32x2 splat operand comes straight from one LDS.128: inner loop is
// 4 LDS.128 + 16 fma.rn.f32x2 per k-step (32 MACs). Register-prefetch
// double buffering on the global loads.
// ---------------------------------------------------------------------------
#define FMA2(d, a, b) asm("fma.rn.f32x2 %0, %1, %2, %0;" : "+l"(d) : "l"(a), "l"(b))

template<bool RELU, bool RES>
__global__ __launch_bounds__(256)
void gemm2(const float* __restrict__ A1, const float* __restrict__ W1, int K1,
           const float* __restrict__ A2, const float* __restrict__ W2, int K2,
           const float* __restrict__ bias, const float* __restrict__ res,
           float* __restrict__ C, int M) {
    constexpr int BM = 128, BK = 16, RS = 132;   // RS: padded row stride (floats)
    __shared__ __align__(16) float As[BK * RS];  // As[k][m], m contiguous
    __shared__ __align__(16) float Wd[BK * RS];  // Wd[k][2n]=Wd[k][2n+1]=W[k][n]

    const int tid = threadIdx.x;
    const int tx = tid & 15, ty = tid >> 4;
    const int row0 = blockIdx.y * BM, col0 = blockIdx.x * 64;
    const int lr = tid >> 2, lk = (tid & 3) * 4;   // A-load: row, kcol
    const int wr = tid >> 4, wc = tid & 15;        // W-load: krow, colgroup

    unsigned long long acc[4][4];
#pragma unroll
    for (int p = 0; p < 4; p++)
#pragma unroll
        for (int j = 0; j < 4; j++) acc[p][j] = 0ull;

#pragma unroll 1
    for (int pass = 0; pass < 2; pass++) {
        const float* A = pass ? A2 : A1;
        const float* W = pass ? W2 : W1;
        const int K = pass ? K2 : K1;
        if (K == 0) continue;

        const int r0 = row0 + lr, r1 = row0 + 64 + lr;
        float4 a0, a1, w;
        a0 = (r0 < M) ? *(const float4*)(A + (size_t)r0 * K + lk) : make_float4(0.f, 0.f, 0.f, 0.f);
        a1 = (r1 < M) ? *(const float4*)(A + (size_t)r1 * K + lk) : make_float4(0.f, 0.f, 0.f, 0.f);
        w  = *(const float4*)(W + (size_t)wr * DOUT + col0 + wc * 4);

        for (int k0 = 0; k0 < K; k0 += BK) {
            __syncthreads();
            As[(lk + 0) * RS + lr] = a0.x;
            As[(lk + 1) * RS + lr] = a0.y;
            As[(lk + 2) * RS + lr] = a0.z;
            As[(lk + 3) * RS + lr] = a0.w;
            As[(lk + 0) * RS + 64 + lr] = a1.x;
            As[(lk + 1) * RS + 64 + lr] = a1.y;
            As[(lk + 2) * RS + 64 + lr] = a1.z;
            As[(lk + 3) * RS + 64 + lr] = a1.w;
            *(float4*)&Wd[wr * RS + wc * 8]     = make_float4(w.x, w.x, w.y, w.y);
            *(float4*)&Wd[wr * RS + wc * 8 + 4] = make_float4(w.z, w.z, w.w, w.w);
            __syncthreads();

            const int kn = k0 + BK;
            if (kn < K) {   // prefetch next tile into regs (overlaps compute)
                a0 = (r0 < M) ? *(const float4*)(A + (size_t)r0 * K + kn + lk) : make_float4(0.f, 0.f, 0.f, 0.f);
                a1 = (r1 < M) ? *(const float4*)(A + (size_t)r1 * K + kn + lk) : make_float4(0.f, 0.f, 0.f, 0.f);
                w  = *(const float4*)(W + (size_t)(kn + wr) * DOUT + col0 + wc * 4);
            }

#pragma unroll
            for (int kk = 0; kk < BK; kk++) {
                const float* ar = &As[kk * RS + ty * 8];
                const float* br = &Wd[kk * RS + tx * 8];
                ulonglong2 A01 = *(const ulonglong2*)ar;
                ulonglong2 A23 = *(const ulonglong2*)(ar + 4);
                ulonglong2 B01 = *(const ulonglong2*)br;
                ulonglong2 B23 = *(const ulonglong2*)(br + 4);
                FMA2(acc[0][0], A01.x, B01.x); FMA2(acc[0][1], A01.x, B01.y);
                FMA2(acc[0][2], A01.x, B23.x); FMA2(acc[0][3], A01.x, B23.y);
                FMA2(acc[1][0], A01.y, B01.x); FMA2(acc[1][1], A01.y, B01.y);
                FMA2(acc[1][2], A01.y, B23.x); FMA2(acc[1][3], A01.y, B23.y);
                FMA2(acc[2][0], A23.x, B01.x); FMA2(acc[2][1], A23.x, B01.y);
                FMA2(acc[2][2], A23.x, B23.x); FMA2(acc[2][3], A23.x, B23.y);
                FMA2(acc[3][0], A23.y, B01.x); FMA2(acc[3][1], A23.y, B01.y);
                FMA2(acc[3][2], A23.y, B23.x); FMA2(acc[3][3], A23.y, B23.y);
            }
        }
    }

    // epilogue: +bias, relu, +residual; float4 stores per row
    const float4 bv = *(const float4*)(bias + col0 + tx * 4);
#pragma unroll
    for (int p = 0; p < 4; p++) {
        float2 f0 = *(float2*)&acc[p][0];
        float2 f1 = *(float2*)&acc[p][1];
        float2 f2 = *(float2*)&acc[p][2];
        float2 f3 = *(float2*)&acc[p][3];
        int r0 = row0 + ty * 8 + 2 * p;
        if (r0 < M) {
            float4 v = make_float4(f0.x + bv.x, f1.x + bv.y, f2.x + bv.z, f3.x + bv.w);
            if (RELU) { v.x = fmaxf(v.x, 0.f); v.y = fmaxf(v.y, 0.f); v.z = fmaxf(v.z, 0.f); v.w = fmaxf(v.w, 0.f); }
            if (RES) {
                float4 rr = *(const float4*)(res + (size_t)r0 * DOUT + col0 + tx * 4);
                v.x += rr.x; v.y += rr.y; v.z += rr.z; v.w += rr.w;
            }
            *(float4*)(C + (size_t)r0 * DOUT + col0 + tx * 4) = v;
        }
        int r1 = r0 + 1;
        if (r1 < M) {
            float4 v = make_float4(f0.y + bv.x, f1.y + bv.y, f2.y + bv.z, f3.y + bv.w);
            if (RELU) { v.x = fmaxf(v.x, 0.f); v.y = fmaxf(v.y, 0.f); v.z = fmaxf(v.z, 0.f); v.w = fmaxf(v.w, 0.f); }
            if (RES) {
                float4 rr = *(const float4*)(res + (size_t)r1 * DOUT + col0 + tx * 4);
                v.x += rr.x; v.y += rr.y; v.z += rr.z; v.w += rr.w;
            }
            *(float4*)(C + (size_t)r1 * DOUT + col0 + tx * 4) = v;
        }
    }
}

// ---------------------------------------------------------------------------
// Launch: edge decode + CSR build (once) ; h = x@W0+b0 ;
//   conv1: gather(h) -> mean ; out1 = relu(mean@Wl1 + h@Wr1 + bl1) + h
//   conv2: gather(out1) -> mean ; out2 = mean@Wl2 + out1@Wr2 + bl2 + out1
// ---------------------------------------------------------------------------
extern "C" void kernel_launch(void* const* d_in, const int* in_sizes, int n_in,
                              void* d_out, int out_size) {
    const float* x   = (const float*)d_in[0];
    const int*   ei  = (const int*)d_in[1];
    const float* W0  = (const float*)d_in[2];
    const float* b0  = (const float*)d_in[3];
    const float* Wl1 = (const float*)d_in[4];
    const float* bl1 = (const float*)d_in[5];
    const float* Wr1 = (const float*)d_in[6];
    const float* Wl2 = (const float*)d_in[7];
    const float* bl2 = (const float*)d_in[8];
    const float* Wr2 = (const float*)d_in[9];

    float* out1 = (float*)d_out;
    float* out2 = out1 + (size_t)NN * DOUT;

    float *h, *mean, *invdeg;
    int *degi, *off, *cur, *src, *dst, *csr;
    cudaGetSymbolAddress((void**)&h,      g_h);
    cudaGetSymbolAddress((void**)&mean,   g_mean);
    cudaGetSymbolAddress((void**)&invdeg, g_invdeg);
    cudaGetSymbolAddress((void**)&degi,   g_degi);
    cudaGetSymbolAddress((void**)&off,    g_off);
    cudaGetSymbolAddress((void**)&cur,    g_cur);
    cudaGetSymbolAddress((void**)&src,    g_src);
    cudaGetSymbolAddress((void**)&dst,    g_dst);
    cudaGetSymbolAddress((void**)&csr,    g_csr);

    const int EB = (EE + 255) / 256;           // 1250
    dim3 ggrid(DOUT / 64, (NN + 127) / 128);   // (4, 79)

    detect_kernel<<<1, 256>>>(ei);
    decode_kernel<<<EB, 256>>>(ei, src, dst);
    zero_degi_kernel<<<(NN + 255) / 256, 256>>>(degi);
    degi_kernel<<<EB, 256>>>(dst, degi);
    scan_kernel<<<1, 256>>>(degi, off, cur, invdeg);

    // h = x @ W0 + b0   (6th kernel launch -> ncu capture target)
    gemm2<false, false><<<ggrid, 256>>>(x, W0, DIN,
                                        nullptr, nullptr, 0,
                                        b0, nullptr, h, NN);

    fill_kernel<<<EB, 256>>>(src, dst, cur, csr);

    // conv1
    gather_kernel<<<NN, 64>>>(h, csr, off, degi, invdeg, mean);
    gemm2<true, true><<<ggrid, 256>>>(mean, Wl1, DOUT,
                                      h, Wr1, DOUT,
                                      bl1, h, out1, NN);

    // conv2
    gather_kernel<<<NN, 64>>>(out1, csr, off, degi, invdeg, mean);
    gemm2<false, true><<<ggrid, 256>>>(mean, Wl2, DOUT,
                                       out1, Wr2, DOUT,
                                       bl2, out1, out2, NN);
}

// round 4
// speedup vs baseline: 1.0763x; 1.0763x over previous
#include <cuda_runtime.h>
#include <cstddef>

constexpr int NN   = 10000;
constexpr int EE   = 320000;
constexpr int DIN  = 512;
constexpr int DOUT = 256;

// Scratch (no allocations allowed) — __device__ globals.
__device__ float g_h[(size_t)NN * DOUT];
__device__ float g_mean[(size_t)NN * DOUT];
__device__ float g_invdeg[NN];
__device__ int   g_degi[NN];
__device__ int   g_off[NN];
__device__ int   g_cur[NN];
__device__ int   g_src[EE];
__device__ int   g_dst[EE];
__device__ int   g_csr[EE];
__device__ int   g_is64;

// ---------------------------------------------------------------------------
// Edge-index dtype detection (int64 vs int32): odd 32-bit words of the first
// 1024 entries are all zero iff data is int64 with node ids < 2^31.
// ---------------------------------------------------------------------------
__global__ void detect_kernel(const int* __restrict__ raw) {
    int nz = 0;
    for (int i = threadIdx.x; i < 1024; i += blockDim.x)
        nz |= (raw[2 * i + 1] != 0);
    nz = __syncthreads_or(nz);
    if (threadIdx.x == 0) g_is64 = nz ? 0 : 1;
}

// Decode edge_index into int32 src/dst AND build the in-degree histogram.
__global__ void decode_degi_kernel(const int* __restrict__ raw,
                                   int* __restrict__ src, int* __restrict__ dst,
                                   int* __restrict__ degi) {
    int e = blockIdx.x * blockDim.x + threadIdx.x;
    if (e >= EE) return;
    int s, d;
    if (g_is64) { s = raw[2 * e]; d = raw[2 * (EE + e)]; }
    else        { s = raw[e];     d = raw[EE + e]; }
    src[e] = s;
    dst[e] = d;
    atomicAdd(&degi[d], 1);
}

// ---------------------------------------------------------------------------
// Single-block exclusive scan over degrees -> CSR offsets + fill cursors +
// invdeg. 256 threads x 40 nodes each.
// ---------------------------------------------------------------------------
__global__ void scan_kernel(const int* __restrict__ degi, int* __restrict__ off,
                            int* __restrict__ cur, float* __restrict__ invdeg) {
    __shared__ int part[256];
    const int t = threadIdx.x;
    const int CH = (NN + 255) / 256;   // 40
    const int s0 = t * CH;
    int sum = 0;
    for (int j = 0; j < CH; j++) {
        int i = s0 + j;
        if (i < NN) sum += degi[i];
    }
    part[t] = sum;
    __syncthreads();
    for (int d = 1; d < 256; d <<= 1) {
        int v = (t >= d) ? part[t - d] : 0;
        __syncthreads();
        part[t] += v;
        __syncthreads();
    }
    int run = (t > 0) ? part[t - 1] : 0;
    for (int j = 0; j < CH; j++) {
        int i = s0 + j;
        if (i < NN) {
            off[i] = run;
            cur[i] = run;
            int d = degi[i];
            run += d;
            invdeg[i] = 1.0f / fmaxf((float)d, 1.0f);
        }
    }
}

__global__ void fill_kernel(const int* __restrict__ src, const int* __restrict__ dst,
                            int* __restrict__ cur, int* __restrict__ csr) {
    int e = blockIdx.x * blockDim.x + threadIdx.x;
    if (e < EE) {
        int p = atomicAdd(&cur[dst[e]], 1);
        csr[p] = src[e];
    }
}

// ---------------------------------------------------------------------------
// CSR gather aggregation: mean[i] = (1/deg_i) * sum_{e in in(i)} h[src(e)].
// One 64-thread block per node, one float4 column chunk per thread.
// Pure gather (L2-resident), no atomics, writes only 10 MB.
// ---------------------------------------------------------------------------
__global__ void gather_kernel(const float* __restrict__ h,
                              const int* __restrict__ csr,
                              const int* __restrict__ off,
                              const int* __restrict__ degi,
                              const float* __restrict__ invdeg,
                              float* __restrict__ mean) {
    const int node = blockIdx.x;
    const int t = threadIdx.x;               // 0..63
    const int base = off[node];
    const int n = degi[node];
    const float4* hp = (const float4*)h;
    float4 acc = make_float4(0.f, 0.f, 0.f, 0.f);
    int e = 0;
    for (; e + 4 <= n; e += 4) {
        int s0 = csr[base + e + 0];
        int s1 = csr[base + e + 1];
        int s2 = csr[base + e + 2];
        int s3 = csr[base + e + 3];
        float4 v0 = hp[(size_t)s0 * 64 + t];
        float4 v1 = hp[(size_t)s1 * 64 + t];
        float4 v2 = hp[(size_t)s2 * 64 + t];
        float4 v3 = hp[(size_t)s3 * 64 + t];
        acc.x += (v0.x + v1.x) + (v2.x + v3.x);
        acc.y += (v0.y + v1.y) + (v2.y + v3.y);
        acc.z += (v0.z + v1.z) + (v2.z + v3.z);
        acc.w += (v0.w + v1.w) + (v2.w + v3.w);
    }
    for (; e < n; e++) {
        int s = csr[base + e];
        float4 v = hp[(size_t)s * 64 + t];
        acc.x += v.x; acc.y += v.y; acc.z += v.z; acc.w += v.w;
    }
    const float s = invdeg[node];
    float4 o = make_float4(acc.x * s, acc.y * s, acc.z * s, acc.w * s);
    ((float4*)mean)[(size_t)node * 64 + t] = o;
}

// ---------------------------------------------------------------------------
// Scalar-FFMA fused dual-GEMM: C = op( A1@W1 + A2@W2 + bias ) [+ res]
// BM=64, BN=128, BK=16, 256 threads, per-thread 4x8 micro-tile.
// Inner loop per k: 1 LDS.128 (A) + 2 LDS.128 (B) + 32 FFMA  -> ~91% of the
// fp32 FFMA issue bound. Register prefetch double-buffers the global loads.
// ---------------------------------------------------------------------------
template<bool RELU, bool RES>
__global__ __launch_bounds__(256)
void gemm_fused(const float* __restrict__ A1, const float* __restrict__ W1, int K1,
                const float* __restrict__ A2, const float* __restrict__ W2, int K2,
                const float* __restrict__ bias, const float* __restrict__ res,
                float* __restrict__ C, int M) {
    constexpr int BM = 64, BK = 16, ASTR = 68;   // 68 floats = 272B, 16B-aligned rows
    __shared__ __align__(16) float As[BK * ASTR];   // As[k][m]
    __shared__ __align__(16) float Bs[BK * 128];    // Bs[k][n]

    const int tid = threadIdx.x;
    const int tx = tid & 15;        // col group -> cols tx*8 .. tx*8+7
    const int ty = tid >> 4;        // row group -> rows ty*4 .. ty*4+3
    const int row0 = blockIdx.y * BM, col0 = blockIdx.x * 128;
    const int lr = tid >> 2, lk = (tid & 3) * 4;   // A-load: row 0..63, kcol
    const int wr = tid >> 4, wc = tid & 15;        // B-load: krow 0..15, colgroup

    float acc[4][8];
#pragma unroll
    for (int i = 0; i < 4; i++)
#pragma unroll
        for (int j = 0; j < 8; j++) acc[i][j] = 0.f;

#pragma unroll 1
    for (int pass = 0; pass < 2; pass++) {
        const float* A = pass ? A2 : A1;
        const float* W = pass ? W2 : W1;
        const int K = pass ? K2 : K1;
        if (K == 0) continue;

        const int grow = row0 + lr;
        float4 a, w0, w1;
        a  = (grow < M) ? *(const float4*)(A + (size_t)grow * K + lk)
                        : make_float4(0.f, 0.f, 0.f, 0.f);
        w0 = *(const float4*)(W + (size_t)wr * DOUT + col0 + wc * 4);
        w1 = *(const float4*)(W + (size_t)wr * DOUT + col0 + 64 + wc * 4);

        for (int k0 = 0; k0 < K; k0 += BK) {
            __syncthreads();
            As[(lk + 0) * ASTR + lr] = a.x;
            As[(lk + 1) * ASTR + lr] = a.y;
            As[(lk + 2) * ASTR + lr] = a.z;
            As[(lk + 3) * ASTR + lr] = a.w;
            *(float4*)&Bs[wr * 128 + wc * 4]      = w0;
            *(float4*)&Bs[wr * 128 + 64 + wc * 4] = w1;
            __syncthreads();

            const int kn = k0 + BK;
            if (kn < K) {   // prefetch next tile into regs (overlaps compute)
                a  = (grow < M) ? *(const float4*)(A + (size_t)grow * K + kn + lk)
                                : make_float4(0.f, 0.f, 0.f, 0.f);
                w0 = *(const float4*)(W + (size_t)(kn + wr) * DOUT + col0 + wc * 4);
                w1 = *(const float4*)(W + (size_t)(kn + wr) * DOUT + col0 + 64 + wc * 4);
            }

#pragma unroll
            for (int kk = 0; kk < BK; kk++) {
                float4 av = *(const float4*)&As[kk * ASTR + ty * 4];
                float4 b0 = *(const float4*)&Bs[kk * 128 + tx * 8];
                float4 b1 = *(const float4*)&Bs[kk * 128 + tx * 8 + 4];
                const float ar[4] = {av.x, av.y, av.z, av.w};
                const float br[8] = {b0.x, b0.y, b0.z, b0.w, b1.x, b1.y, b1.z, b1.w};
#pragma unroll
                for (int i = 0; i < 4; i++)
#pragma unroll
                    for (int j = 0; j < 8; j++)
                        acc[i][j] = fmaf(ar[i], br[j], acc[i][j]);
            }
        }
    }

    // epilogue: +bias, relu, +residual; two float4 stores per row
    const float4 bv0 = *(const float4*)(bias + col0 + tx * 8);
    const float4 bv1 = *(const float4*)(bias + col0 + tx * 8 + 4);
#pragma unroll
    for (int i = 0; i < 4; i++) {
        const int row = row0 + ty * 4 + i;
        if (row >= M) continue;
        float4 v0 = make_float4(acc[i][0] + bv0.x, acc[i][1] + bv0.y,
                                acc[i][2] + bv0.z, acc[i][3] + bv0.w);
        float4 v1 = make_float4(acc[i][4] + bv1.x, acc[i][5] + bv1.y,
                                acc[i][6] + bv1.z, acc[i][7] + bv1.w);
        if (RELU) {
            v0.x = fmaxf(v0.x, 0.f); v0.y = fmaxf(v0.y, 0.f);
            v0.z = fmaxf(v0.z, 0.f); v0.w = fmaxf(v0.w, 0.f);
            v1.x = fmaxf(v1.x, 0.f); v1.y = fmaxf(v1.y, 0.f);
            v1.z = fmaxf(v1.z, 0.f); v1.w = fmaxf(v1.w, 0.f);
        }
        if (RES) {
            float4 r0 = *(const float4*)(res + (size_t)row * DOUT + col0 + tx * 8);
            float4 r1 = *(const float4*)(res + (size_t)row * DOUT + col0 + tx * 8 + 4);
            v0.x += r0.x; v0.y += r0.y; v0.z += r0.z; v0.w += r0.w;
            v1.x += r1.x; v1.y += r1.y; v1.z += r1.z; v1.w += r1.w;
        }
        *(float4*)(C + (size_t)row * DOUT + col0 + tx * 8)     = v0;
        *(float4*)(C + (size_t)row * DOUT + col0 + tx * 8 + 4) = v1;
    }
}

// ---------------------------------------------------------------------------
// Launch (gemm1 is the 4th kernel launch -> ncu capture target):
//   detect ; decode+degi ; scan ; gemm1 ; fill ;
//   conv1: gather -> gemm2 ; conv2: gather -> gemm3
// ---------------------------------------------------------------------------
extern "C" void kernel_launch(void* const* d_in, const int* in_sizes, int n_in,
                              void* d_out, int out_size) {
    const float* x   = (const float*)d_in[0];
    const int*   ei  = (const int*)d_in[1];
    const float* W0  = (const float*)d_in[2];
    const float* b0  = (const float*)d_in[3];
    const float* Wl1 = (const float*)d_in[4];
    const float* bl1 = (const float*)d_in[5];
    const float* Wr1 = (const float*)d_in[6];
    const float* Wl2 = (const float*)d_in[7];
    const float* bl2 = (const float*)d_in[8];
    const float* Wr2 = (const float*)d_in[9];

    float* out1 = (float*)d_out;
    float* out2 = out1 + (size_t)NN * DOUT;

    float *h, *mean, *invdeg;
    int *degi, *off, *cur, *src, *dst, *csr;
    cudaGetSymbolAddress((void**)&h,      g_h);
    cudaGetSymbolAddress((void**)&mean,   g_mean);
    cudaGetSymbolAddress((void**)&invdeg, g_invdeg);
    cudaGetSymbolAddress((void**)&degi,   g_degi);
    cudaGetSymbolAddress((void**)&off,    g_off);
    cudaGetSymbolAddress((void**)&cur,    g_cur);
    cudaGetSymbolAddress((void**)&src,    g_src);
    cudaGetSymbolAddress((void**)&dst,    g_dst);
    cudaGetSymbolAddress((void**)&csr,    g_csr);

    const int EB = (EE + 255) / 256;             // 1250
    dim3 ggrid(DOUT / 128, (NN + 63) / 64);      // (2, 157)

    detect_kernel<<<1, 256>>>(ei);                                   // launch 1
    cudaMemsetAsync(degi, 0, NN * sizeof(int));
    decode_degi_kernel<<<EB, 256>>>(ei, src, dst, degi);             // launch 2
    scan_kernel<<<1, 256>>>(degi, off, cur, invdeg);                 // launch 3

    // h = x @ W0 + b0   — launch 4 (ncu capture target)
    gemm_fused<false, false><<<ggrid, 256>>>(x, W0, DIN,
                                             nullptr, nullptr, 0,
                                             b0, nullptr, h, NN);

    fill_kernel<<<EB, 256>>>(src, dst, cur, csr);                    // launch 5

    // conv1
    gather_kernel<<<NN, 64>>>(h, csr, off, degi, invdeg, mean);
    gemm_fused<true, true><<<ggrid, 256>>>(mean, Wl1, DOUT,
                                           h, Wr1, DOUT,
                                           bl1, h, out1, NN);

    // conv2
    gather_kernel<<<NN, 64>>>(out1, csr, off, degi, invdeg, mean);
    gemm_fused<false, true><<<ggrid, 256>>>(mean, Wl2, DOUT,
                                            out1, Wr2, DOUT,
                                            bl2, out1, out2, NN);
}

// round 5
// speedup vs baseline: 1.4623x; 1.3587x over previous
#include <cuda_runtime.h>
#include <cstddef>

constexpr int NN   = 10000;
constexpr int EE   = 320000;
constexpr int DIN  = 512;
constexpr int DOUT = 256;

// Scratch (no allocations allowed) — __device__ globals.
__device__ float g_h[(size_t)NN * DOUT];
__device__ float g_mean[(size_t)NN * DOUT];
__device__ float g_invdeg[NN];
__device__ int   g_degi[NN];
__device__ int   g_off[NN];
__device__ int   g_cur[NN];
__device__ int   g_src[EE];
__device__ int   g_dst[EE];
__device__ int   g_csr[EE];
__device__ int   g_is64;

// ---------------------------------------------------------------------------
// Edge-index dtype detection (int64 vs int32): odd 32-bit words of the first
// 1024 entries are all zero iff data is int64 with node ids < 2^31.
// ---------------------------------------------------------------------------
__global__ void detect_kernel(const int* __restrict__ raw) {
    int nz = 0;
    for (int i = threadIdx.x; i < 1024; i += blockDim.x)
        nz |= (raw[2 * i + 1] != 0);
    nz = __syncthreads_or(nz);
    if (threadIdx.x == 0) g_is64 = nz ? 0 : 1;
}

// Decode edge_index into int32 src/dst AND build the in-degree histogram.
__global__ void decode_degi_kernel(const int* __restrict__ raw,
                                   int* __restrict__ src, int* __restrict__ dst,
                                   int* __restrict__ degi) {
    int e = blockIdx.x * blockDim.x + threadIdx.x;
    if (e >= EE) return;
    int s, d;
    if (g_is64) { s = raw[2 * e]; d = raw[2 * (EE + e)]; }
    else        { s = raw[e];     d = raw[EE + e]; }
    src[e] = s;
    dst[e] = d;
    atomicAdd(&degi[d], 1);
}

// ---------------------------------------------------------------------------
// Single-block exclusive scan over degrees -> CSR offsets + fill cursors +
// invdeg. 256 threads x 40 nodes each.
// ---------------------------------------------------------------------------
__global__ void scan_kernel(const int* __restrict__ degi, int* __restrict__ off,
                            int* __restrict__ cur, float* __restrict__ invdeg) {
    __shared__ int part[256];
    const int t = threadIdx.x;
    const int CH = (NN + 255) / 256;   // 40
    const int s0 = t * CH;
    int sum = 0;
    for (int j = 0; j < CH; j++) {
        int i = s0 + j;
        if (i < NN) sum += degi[i];
    }
    part[t] = sum;
    __syncthreads();
    for (int d = 1; d < 256; d <<= 1) {
        int v = (t >= d) ? part[t - d] : 0;
        __syncthreads();
        part[t] += v;
        __syncthreads();
    }
    int run = (t > 0) ? part[t - 1] : 0;
    for (int j = 0; j < CH; j++) {
        int i = s0 + j;
        if (i < NN) {
            off[i] = run;
            cur[i] = run;
            int d = degi[i];
            run += d;
            invdeg[i] = 1.0f / fmaxf((float)d, 1.0f);
        }
    }
}

__global__ void fill_kernel(const int* __restrict__ src, const int* __restrict__ dst,
                            int* __restrict__ cur, int* __restrict__ csr) {
    int e = blockIdx.x * blockDim.x + threadIdx.x;
    if (e < EE) {
        int p = atomicAdd(&cur[dst[e]], 1);
        csr[p] = src[e];
    }
}

// ---------------------------------------------------------------------------
// CSR gather aggregation: mean[i] = (1/deg_i) * sum_{e in in(i)} h[src(e)].
// One 64-thread block per node, one float4 column chunk per thread.
// Pure gather (L2-resident), no atomics, writes only 10 MB.
// ---------------------------------------------------------------------------
__global__ void gather_kernel(const float* __restrict__ h,
                              const int* __restrict__ csr,
                              const int* __restrict__ off,
                              const int* __restrict__ degi,
                              const float* __restrict__ invdeg,
                              float* __restrict__ mean) {
    const int node = blockIdx.x;
    const int t = threadIdx.x;               // 0..63
    const int base = off[node];
    const int n = degi[node];
    const float4* hp = (const float4*)h;
    float4 acc = make_float4(0.f, 0.f, 0.f, 0.f);
    int e = 0;
    for (; e + 4 <= n; e += 4) {
        int s0 = csr[base + e + 0];
        int s1 = csr[base + e + 1];
        int s2 = csr[base + e + 2];
        int s3 = csr[base + e + 3];
        float4 v0 = hp[(size_t)s0 * 64 + t];
        float4 v1 = hp[(size_t)s1 * 64 + t];
        float4 v2 = hp[(size_t)s2 * 64 + t];
        float4 v3 = hp[(size_t)s3 * 64 + t];
        acc.x += (v0.x + v1.x) + (v2.x + v3.x);
        acc.y += (v0.y + v1.y) + (v2.y + v3.y);
        acc.z += (v0.z + v1.z) + (v2.z + v3.z);
        acc.w += (v0.w + v1.w) + (v2.w + v3.w);
    }
    for (; e < n; e++) {
        int s = csr[base + e];
        float4 v = hp[(size_t)s * 64 + t];
        acc.x += v.x; acc.y += v.y; acc.z += v.z; acc.w += v.w;
    }
    const float s = invdeg[node];
    float4 o = make_float4(acc.x * s, acc.y * s, acc.z * s, acc.w * s);
    ((float4*)mean)[(size_t)node * 64 + t] = o;
}

// ---------------------------------------------------------------------------
// Fused dual-GEMM (R2 shape — the fastest measured): C = op(A1@W1 + A2@W2
// + bias) [+ res].  BM=BN=64, BK=16, 256 threads, 4x4 micro-tile, ~40 regs
// -> 5-6 blocks/SM; grid 628 -> 4.2 blocks/SM, wave tail amortized.
// Register prefetch double-buffers global loads.
// ---------------------------------------------------------------------------
template<bool RELU, bool RES>
__global__ void gemm_fused(const float* __restrict__ A1, const float* __restrict__ W1, int K1,
                           const float* __restrict__ A2, const float* __restrict__ W2, int K2,
                           const float* __restrict__ bias, const float* __restrict__ res,
                           float* __restrict__ C, int M) {
    __shared__ float As[16][65];   // padded to dodge store conflicts
    __shared__ float Ws[16][64];

    const int tid = threadIdx.x;
    const int tx = tid & 15;       // 0..15 (col group)
    const int ty = tid >> 4;       // 0..15 (row group)
    const int row0 = blockIdx.y * 64;
    const int col0 = blockIdx.x * 64;

    float acc[4][4];
#pragma unroll
    for (int i = 0; i < 4; i++)
#pragma unroll
        for (int j = 0; j < 4; j++) acc[i][j] = 0.f;

    const int lr = tid >> 2;          // A-tile row   0..63
    const int lk = (tid & 3) * 4;     // A-tile kcol  0,4,8,12
    const int wr = tid >> 4;          // W-tile row   0..15
    const int wc = (tid & 15) * 4;    // W-tile col

#pragma unroll 1
    for (int pass = 0; pass < 2; pass++) {
        const float* A = pass ? A2 : A1;
        const float* W = pass ? W2 : W1;
        const int K = pass ? K2 : K1;
        if (K == 0) continue;

        const int grow = row0 + lr;
        float4 a, w;
        a = (grow < M) ? *(const float4*)(A + (size_t)grow * K + lk)
                       : make_float4(0.f, 0.f, 0.f, 0.f);
        w = *(const float4*)(W + (size_t)wr * DOUT + col0 + wc);

        for (int k0 = 0; k0 < K; k0 += 16) {
            __syncthreads();
            As[lk + 0][lr] = a.x;
            As[lk + 1][lr] = a.y;
            As[lk + 2][lr] = a.z;
            As[lk + 3][lr] = a.w;
            *(float4*)&Ws[wr][wc] = w;
            __syncthreads();

            const int kn = k0 + 16;
            if (kn < K) {   // prefetch next tile into regs (overlaps compute)
                a = (grow < M) ? *(const float4*)(A + (size_t)grow * K + kn + lk)
                               : make_float4(0.f, 0.f, 0.f, 0.f);
                w = *(const float4*)(W + (size_t)(kn + wr) * DOUT + col0 + wc);
            }

#pragma unroll
            for (int kk = 0; kk < 16; kk++) {
                float a0 = As[kk][ty * 4 + 0];
                float a1 = As[kk][ty * 4 + 1];
                float a2 = As[kk][ty * 4 + 2];
                float a3 = As[kk][ty * 4 + 3];
                float4 b = *(const float4*)&Ws[kk][tx * 4];
                acc[0][0] += a0 * b.x; acc[0][1] += a0 * b.y; acc[0][2] += a0 * b.z; acc[0][3] += a0 * b.w;
                acc[1][0] += a1 * b.x; acc[1][1] += a1 * b.y; acc[1][2] += a1 * b.z; acc[1][3] += a1 * b.w;
                acc[2][0] += a2 * b.x; acc[2][1] += a2 * b.y; acc[2][2] += a2 * b.z; acc[2][3] += a2 * b.w;
                acc[3][0] += a3 * b.x; acc[3][1] += a3 * b.y; acc[3][2] += a3 * b.z; acc[3][3] += a3 * b.w;
            }
        }
    }

    // epilogue: +bias, relu, +residual
    const float4 bv = *(const float4*)(bias + col0 + tx * 4);
#pragma unroll
    for (int i = 0; i < 4; i++) {
        const int row = row0 + ty * 4 + i;
        if (row >= M) continue;
        float4 v = make_float4(acc[i][0] + bv.x, acc[i][1] + bv.y,
                               acc[i][2] + bv.z, acc[i][3] + bv.w);
        if (RELU) {
            v.x = fmaxf(v.x, 0.f); v.y = fmaxf(v.y, 0.f);
            v.z = fmaxf(v.z, 0.f); v.w = fmaxf(v.w, 0.f);
        }
        if (RES) {
            float4 r = *(const float4*)(res + (size_t)row * DOUT + col0 + tx * 4);
            v.x += r.x; v.y += r.y; v.z += r.z; v.w += r.w;
        }
        *(float4*)(C + (size_t)row * DOUT + col0 + tx * 4) = v;
    }
}

// ---------------------------------------------------------------------------
// Launch (gemm1 is the 4th kernel launch -> ncu capture target):
//   detect ; decode+degi ; scan ; gemm1 ; fill ;
//   conv1: gather -> gemm2 ; conv2: gather -> gemm3
// ---------------------------------------------------------------------------
extern "C" void kernel_launch(void* const* d_in, const int* in_sizes, int n_in,
                              void* d_out, int out_size) {
    const float* x   = (const float*)d_in[0];
    const int*   ei  = (const int*)d_in[1];
    const float* W0  = (const float*)d_in[2];
    const float* b0  = (const float*)d_in[3];
    const float* Wl1 = (const float*)d_in[4];
    const float* bl1 = (const float*)d_in[5];
    const float* Wr1 = (const float*)d_in[6];
    const float* Wl2 = (const float*)d_in[7];
    const float* bl2 = (const float*)d_in[8];
    const float* Wr2 = (const float*)d_in[9];

    float* out1 = (float*)d_out;
    float* out2 = out1 + (size_t)NN * DOUT;

    float *h, *mean, *invdeg;
    int *degi, *off, *cur, *src, *dst, *csr;
    cudaGetSymbolAddress((void**)&h,      g_h);
    cudaGetSymbolAddress((void**)&mean,   g_mean);
    cudaGetSymbolAddress((void**)&invdeg, g_invdeg);
    cudaGetSymbolAddress((void**)&degi,   g_degi);
    cudaGetSymbolAddress((void**)&off,    g_off);
    cudaGetSymbolAddress((void**)&cur,    g_cur);
    cudaGetSymbolAddress((void**)&src,    g_src);
    cudaGetSymbolAddress((void**)&dst,    g_dst);
    cudaGetSymbolAddress((void**)&csr,    g_csr);

    const int EB = (EE + 255) / 256;             // 1250
    dim3 ggrid(DOUT / 64, (NN + 63) / 64);       // (4, 157) = 628 blocks

    detect_kernel<<<1, 256>>>(ei);                                   // launch 1
    cudaMemsetAsync(degi, 0, NN * sizeof(int));
    decode_degi_kernel<<<EB, 256>>>(ei, src, dst, degi);             // launch 2
    scan_kernel<<<1, 256>>>(degi, off, cur, invdeg);                 // launch 3

    // h = x @ W0 + b0   — launch 4 (ncu capture target)
    gemm_fused<false, false><<<ggrid, 256>>>(x, W0, DIN,
                                             nullptr, nullptr, 0,
                                             b0, nullptr, h, NN);

    fill_kernel<<<EB, 256>>>(src, dst, cur, csr);                    // launch 5

    // conv1
    gather_kernel<<<NN, 64>>>(h, csr, off, degi, invdeg, mean);
    gemm_fused<true, true><<<ggrid, 256>>>(mean, Wl1, DOUT,
                                           h, Wr1, DOUT,
                                           bl1, h, out1, NN);

    // conv2
    gather_kernel<<<NN, 64>>>(out1, csr, off, degi, invdeg, mean);
    gemm_fused<false, true><<<ggrid, 256>>>(mean, Wl2, DOUT,
                                            out1, Wr2, DOUT,
                                            bl2, out1, out2, NN);
}

// round 6
// speedup vs baseline: 1.8759x; 1.2828x over previous
#include <cuda_runtime.h>
#include <cuda_bf16.h>
#include <cstdint>
#include <cstddef>

constexpr int NN   = 10000;
constexpr int EE   = 320000;
constexpr int DIN  = 512;
constexpr int DOUT = 256;

// ---------------- scratch (__device__ globals; no allocs allowed) ----------
__device__ float g_h[(size_t)NN * DOUT];
__device__ float g_invdeg[NN];
__device__ int   g_degi[NN];
__device__ int   g_off[NN];
__device__ int   g_cur[NN];
__device__ int   g_src[EE];
__device__ int   g_dst[EE];
__device__ int   g_csr[EE];
__device__ int   g_is64;

// bf16 hi/lo split operands
__device__ __nv_bfloat16 g_xhi[(size_t)NN * DIN],  g_xlo[(size_t)NN * DIN];
__device__ __nv_bfloat16 g_w0hi[DIN * DOUT],       g_w0lo[DIN * DOUT];
__device__ __nv_bfloat16 g_wl1hi[DOUT * DOUT],     g_wl1lo[DOUT * DOUT];
__device__ __nv_bfloat16 g_wr1hi[DOUT * DOUT],     g_wr1lo[DOUT * DOUT];
__device__ __nv_bfloat16 g_wl2hi[DOUT * DOUT],     g_wl2lo[DOUT * DOUT];
__device__ __nv_bfloat16 g_wr2hi[DOUT * DOUT],     g_wr2lo[DOUT * DOUT];
__device__ __nv_bfloat16 g_hhi[(size_t)NN * DOUT], g_hlo[(size_t)NN * DOUT];
__device__ __nv_bfloat16 g_mhi[(size_t)NN * DOUT], g_mlo[(size_t)NN * DOUT];
__device__ __nv_bfloat16 g_o1hi[(size_t)NN * DOUT], g_o1lo[(size_t)NN * DOUT];

// ---------------------------------------------------------------------------
// Edge-index dtype detection (int64 vs int32).
// ---------------------------------------------------------------------------
__global__ void detect_kernel(const int* __restrict__ raw) {
    int nz = 0;
    for (int i = threadIdx.x; i < 1024; i += blockDim.x)
        nz |= (raw[2 * i + 1] != 0);
    nz = __syncthreads_or(nz);
    if (threadIdx.x == 0) g_is64 = nz ? 0 : 1;
}

// Decode edge_index into int32 src/dst + in-degree histogram.
__global__ void decode_degi_kernel(const int* __restrict__ raw,
                                   int* __restrict__ src, int* __restrict__ dst,
                                   int* __restrict__ degi) {
    int e = blockIdx.x * blockDim.x + threadIdx.x;
    if (e >= EE) return;
    int s, d;
    if (g_is64) { s = raw[2 * e]; d = raw[2 * (EE + e)]; }
    else        { s = raw[e];     d = raw[EE + e]; }
    src[e] = s;
    dst[e] = d;
    atomicAdd(&degi[d], 1);
}

// ---------------------------------------------------------------------------
// bf16 hi/lo split of x and the five weight matrices (one launch).
// ---------------------------------------------------------------------------
__global__ void split_kernel(const float* __restrict__ x,  const float* __restrict__ W0,
                             const float* __restrict__ Wl1, const float* __restrict__ Wr1,
                             const float* __restrict__ Wl2, const float* __restrict__ Wr2) {
    constexpr int S0 = NN * DIN;          // 5,120,000
    constexpr int S1 = DIN * DOUT;        // 131,072
    constexpr int S2 = DOUT * DOUT;       // 65,536
    int i = blockIdx.x * blockDim.x + threadIdx.x;
    const float* src; __nv_bfloat16 *hi, *lo; int off;
    if      (i < S0)                     { src = x;   hi = g_xhi;  lo = g_xlo;  off = i; }
    else if (i < S0 + S1)                { src = W0;  hi = g_w0hi; lo = g_w0lo; off = i - S0; }
    else if (i < S0 + S1 + S2)           { src = Wl1; hi = g_wl1hi; lo = g_wl1lo; off = i - S0 - S1; }
    else if (i < S0 + S1 + 2 * S2)       { src = Wr1; hi = g_wr1hi; lo = g_wr1lo; off = i - S0 - S1 - S2; }
    else if (i < S0 + S1 + 3 * S2)       { src = Wl2; hi = g_wl2hi; lo = g_wl2lo; off = i - S0 - S1 - 2 * S2; }
    else if (i < S0 + S1 + 4 * S2)       { src = Wr2; hi = g_wr2hi; lo = g_wr2lo; off = i - S0 - S1 - 3 * S2; }
    else return;
    float v = src[off];
    __nv_bfloat16 h = __float2bfloat16(v);
    hi[off] = h;
    lo[off] = __float2bfloat16(v - __bfloat162float(h));
}

// ---------------------------------------------------------------------------
// Exclusive scan over degrees -> CSR offsets + cursors + invdeg (1 block).
// ---------------------------------------------------------------------------
__global__ void scan_kernel(const int* __restrict__ degi, int* __restrict__ off,
                            int* __restrict__ cur, float* __restrict__ invdeg) {
    __shared__ int part[256];
    const int t = threadIdx.x;
    const int CH = (NN + 255) / 256;
    const int s0 = t * CH;
    int sum = 0;
    for (int j = 0; j < CH; j++) { int i = s0 + j; if (i < NN) sum += degi[i]; }
    part[t] = sum;
    __syncthreads();
    for (int d = 1; d < 256; d <<= 1) {
        int v = (t >= d) ? part[t - d] : 0;
        __syncthreads();
        part[t] += v;
        __syncthreads();
    }
    int run = (t > 0) ? part[t - 1] : 0;
    for (int j = 0; j < CH; j++) {
        int i = s0 + j;
        if (i < NN) {
            off[i] = run; cur[i] = run;
            int d = degi[i]; run += d;
            invdeg[i] = 1.0f / fmaxf((float)d, 1.0f);
        }
    }
}

__global__ void fill_kernel(const int* __restrict__ src, const int* __restrict__ dst,
                            int* __restrict__ cur, int* __restrict__ csr) {
    int e = blockIdx.x * blockDim.x + threadIdx.x;
    if (e < EE) {
        int p = atomicAdd(&cur[dst[e]], 1);
        csr[p] = src[e];
    }
}

// ---------------------------------------------------------------------------
// CSR gather: mean[i] = invdeg_i * sum h[src(e)], emitted directly as bf16
// hi/lo (the only consumer is the tensor-core GEMM).
// ---------------------------------------------------------------------------
__global__ void gather_kernel(const float* __restrict__ h,
                              const int* __restrict__ csr,
                              const int* __restrict__ off,
                              const int* __restrict__ degi,
                              const float* __restrict__ invdeg,
                              __nv_bfloat16* __restrict__ mhi,
                              __nv_bfloat16* __restrict__ mlo) {
    const int node = blockIdx.x;
    const int t = threadIdx.x;               // 0..63
    const int base = off[node];
    const int n = degi[node];
    const float4* hp = (const float4*)h;
    float4 acc = make_float4(0.f, 0.f, 0.f, 0.f);
    int e = 0;
    for (; e + 4 <= n; e += 4) {
        int s0 = csr[base + e + 0];
        int s1 = csr[base + e + 1];
        int s2 = csr[base + e + 2];
        int s3 = csr[base + e + 3];
        float4 v0 = hp[(size_t)s0 * 64 + t];
        float4 v1 = hp[(size_t)s1 * 64 + t];
        float4 v2 = hp[(size_t)s2 * 64 + t];
        float4 v3 = hp[(size_t)s3 * 64 + t];
        acc.x += (v0.x + v1.x) + (v2.x + v3.x);
        acc.y += (v0.y + v1.y) + (v2.y + v3.y);
        acc.z += (v0.z + v1.z) + (v2.z + v3.z);
        acc.w += (v0.w + v1.w) + (v2.w + v3.w);
    }
    for (; e < n; e++) {
        int s = csr[base + e];
        float4 v = hp[(size_t)s * 64 + t];
        acc.x += v.x; acc.y += v.y; acc.z += v.z; acc.w += v.w;
    }
    const float s = invdeg[node];
    float o[4] = {acc.x * s, acc.y * s, acc.z * s, acc.w * s};
    __nv_bfloat16 hi[4], lo[4];
#pragma unroll
    for (int j = 0; j < 4; j++) {
        hi[j] = __float2bfloat16(o[j]);
        lo[j] = __float2bfloat16(o[j] - __bfloat162float(hi[j]));
    }
    size_t p = (size_t)node * DOUT + t * 4;
    __nv_bfloat162 a, b;
    a.x = hi[0]; a.y = hi[1]; b.x = hi[2]; b.y = hi[3];
    *(__nv_bfloat162*)(mhi + p) = a; *(__nv_bfloat162*)(mhi + p + 2) = b;
    a.x = lo[0]; a.y = lo[1]; b.x = lo[2]; b.y = lo[3];
    *(__nv_bfloat162*)(mlo + p) = a; *(__nv_bfloat162*)(mlo + p + 2) = b;
}

// ---------------------------------------------------------------------------
// Tensor-core GEMM over a list of (A,W) bf16 operand passes (bf16x3 split):
//   C = op( sum_p A_p @ W_p + bias ) [+ res], optional bf16 hi/lo re-split
// Block 128x64, 8 warps (32x32 each), BK=32, mma.sync m16n8k16 bf16->f32.
// ---------------------------------------------------------------------------
struct PassList {
    const __nv_bfloat16* A[6];
    const __nv_bfloat16* W[6];
};

#define LDSM4(d0, d1, d2, d3, addr) \
    asm volatile("ldmatrix.sync.aligned.m8n8.x4.shared.b16 {%0,%1,%2,%3}, [%4];" \
        : "=r"(d0), "=r"(d1), "=r"(d2), "=r"(d3) : "r"(addr))
#define LDSM4T(d0, d1, d2, d3, addr) \
    asm volatile("ldmatrix.sync.aligned.m8n8.x4.trans.shared.b16 {%0,%1,%2,%3}, [%4];" \
        : "=r"(d0), "=r"(d1), "=r"(d2), "=r"(d3) : "r"(addr))
#define MMA16816(c, a, b0, b1) \
    asm volatile("mma.sync.aligned.m16n8k16.row.col.f32.bf16.bf16.f32 " \
        "{%0,%1,%2,%3}, {%4,%5,%6,%7}, {%8,%9}, {%0,%1,%2,%3};" \
        : "+f"(c[0]), "+f"(c[1]), "+f"(c[2]), "+f"(c[3]) \
        : "r"(a[0]), "r"(a[1]), "r"(a[2]), "r"(a[3]), "r"(b0), "r"(b1))

template<int K, int NP, bool RELU, bool RES, bool OUTS>
__global__ __launch_bounds__(256)
void gemm_mma(PassList P, const float* __restrict__ bias, const float* __restrict__ res,
              float* __restrict__ C, __nv_bfloat16* __restrict__ Chi,
              __nv_bfloat16* __restrict__ Clo, int M) {
    constexpr int ASTR = 40;   // halfs; 80B row stride -> conflict-free ldmatrix
    constexpr int WSTR = 72;   // halfs; 144B row stride -> conflict-free ldmatrix
    constexpr int KS = K / 32;
    constexpr int NST = NP * KS;
    __shared__ __align__(16) __nv_bfloat16 As[128 * ASTR];
    __shared__ __align__(16) __nv_bfloat16 Ws[32 * WSTR];

    const int tid = threadIdx.x, wid = tid >> 5, lane = tid & 31;
    const int row0 = blockIdx.y * 128, col0 = blockIdx.x * 64;
    const int mb = (wid & 3) * 32, nb = (wid >> 2) * 32;

    float acc[2][4][4];
#pragma unroll
    for (int mt = 0; mt < 2; mt++)
#pragma unroll
        for (int nt = 0; nt < 4; nt++)
#pragma unroll
            for (int r = 0; r < 4; r++) acc[mt][nt][r] = 0.f;

    // global-load mapping
    const int arow = tid >> 2;            // 0..63 (and +64)
    const int achunk = (tid & 3) * 8;     // half offset within 32-wide tile
    const int wk = tid >> 3;              // 0..31
    const int wn = (tid & 7) * 8;

    const uint32_t asu = (uint32_t)__cvta_generic_to_shared(As);
    const uint32_t wsu = (uint32_t)__cvta_generic_to_shared(Ws);

    const uint4 Z4 = make_uint4(0u, 0u, 0u, 0u);
    uint4 ra0, ra1, rw;

#define LOADSTAGE(S) { \
        int pass = (S) / KS; int k0 = ((S) - pass * KS) * 32; \
        const __nv_bfloat16* Ap = P.A[pass]; const __nv_bfloat16* Wp = P.W[pass]; \
        int r0 = row0 + arow; \
        ra0 = (r0 < M) ? *(const uint4*)(Ap + (size_t)r0 * K + k0 + achunk) : Z4; \
        int r1 = r0 + 64; \
        ra1 = (r1 < M) ? *(const uint4*)(Ap + (size_t)r1 * K + k0 + achunk) : Z4; \
        rw = *(const uint4*)(Wp + (size_t)(k0 + wk) * DOUT + col0 + wn); \
    }

    LOADSTAGE(0);

    for (int s = 0; s < NST; s++) {
        __syncthreads();
        *(uint4*)&As[arow * ASTR + achunk]        = ra0;
        *(uint4*)&As[(arow + 64) * ASTR + achunk] = ra1;
        *(uint4*)&Ws[wk * WSTR + wn]              = rw;
        __syncthreads();
        if (s + 1 < NST) LOADSTAGE(s + 1);

        const int r = lane & 7, selr = lane >> 3;   // ldmatrix addressing
#pragma unroll
        for (int kk = 0; kk < 32; kk += 16) {
            uint32_t a[2][4], bt0[4], bt1[4];
            // A: matrices (m0,k0),(m8,k0),(m0,k8),(m8,k8)
            uint32_t aaddr = asu + ((mb + (selr & 1) * 8 + r) * ASTR + kk + (selr >> 1) * 8) * 2;
            LDSM4(a[0][0], a[0][1], a[0][2], a[0][3], aaddr);
            LDSM4(a[1][0], a[1][1], a[1][2], a[1][3], aaddr + 16 * ASTR * 2);
            // B (trans): matrices (k0,n0),(k8,n0),(k0,n8),(k8,n8)
            uint32_t baddr = wsu + ((kk + (selr & 1) * 8 + r) * WSTR + nb + (selr >> 1) * 8) * 2;
            LDSM4T(bt0[0], bt0[1], bt0[2], bt0[3], baddr);
            LDSM4T(bt1[0], bt1[1], bt1[2], bt1[3], baddr + 16 * 2);
#pragma unroll
            for (int mt = 0; mt < 2; mt++) {
                MMA16816(acc[mt][0], a[mt], bt0[0], bt0[1]);
                MMA16816(acc[mt][1], a[mt], bt0[2], bt0[3]);
                MMA16816(acc[mt][2], a[mt], bt1[0], bt1[1]);
                MMA16816(acc[mt][3], a[mt], bt1[2], bt1[3]);
            }
        }
    }
#undef LOADSTAGE

    // epilogue
    const int g = lane >> 2, tig = lane & 3;
#pragma unroll
    for (int mt = 0; mt < 2; mt++) {
#pragma unroll
        for (int half = 0; half < 2; half++) {
            const int row = row0 + mb + mt * 16 + g + half * 8;
            if (row >= M) continue;
#pragma unroll
            for (int nt = 0; nt < 4; nt++) {
                const int col = col0 + nb + nt * 8 + tig * 2;
                float v0 = acc[mt][nt][half * 2 + 0] + bias[col];
                float v1 = acc[mt][nt][half * 2 + 1] + bias[col + 1];
                if (RELU) { v0 = fmaxf(v0, 0.f); v1 = fmaxf(v1, 0.f); }
                if (RES) {
                    float2 rr = *(const float2*)(res + (size_t)row * DOUT + col);
                    v0 += rr.x; v1 += rr.y;
                }
                float2 o; o.x = v0; o.y = v1;
                *(float2*)(C + (size_t)row * DOUT + col) = o;
                if (OUTS) {
                    __nv_bfloat16 h0 = __float2bfloat16(v0), h1 = __float2bfloat16(v1);
                    __nv_bfloat162 hh; hh.x = h0; hh.y = h1;
                    *(__nv_bfloat162*)(Chi + (size_t)row * DOUT + col) = hh;
                    __nv_bfloat162 ll;
                    ll.x = __float2bfloat16(v0 - __bfloat162float(h0));
                    ll.y = __float2bfloat16(v1 - __bfloat162float(h1));
                    *(__nv_bfloat162*)(Clo + (size_t)row * DOUT + col) = ll;
                }
            }
        }
    }
}

// ---------------------------------------------------------------------------
// Launch: detect(1) decode(2) split(3) gemm1(4=capture) scan fill
//         gather gemm2 gather gemm3
// ---------------------------------------------------------------------------
extern "C" void kernel_launch(void* const* d_in, const int* in_sizes, int n_in,
                              void* d_out, int out_size) {
    const float* x   = (const float*)d_in[0];
    const int*   ei  = (const int*)d_in[1];
    const float* W0  = (const float*)d_in[2];
    const float* b0  = (const float*)d_in[3];
    const float* Wl1 = (const float*)d_in[4];
    const float* bl1 = (const float*)d_in[5];
    const float* Wr1 = (const float*)d_in[6];
    const float* Wl2 = (const float*)d_in[7];
    const float* bl2 = (const float*)d_in[8];
    const float* Wr2 = (const float*)d_in[9];

    float* out1 = (float*)d_out;
    float* out2 = out1 + (size_t)NN * DOUT;

    float *h, *invdeg;
    int *degi, *off, *cur, *src, *dst, *csr;
    __nv_bfloat16 *xhi, *xlo, *w0hi, *w0lo, *wl1hi, *wl1lo, *wr1hi, *wr1lo;
    __nv_bfloat16 *wl2hi, *wl2lo, *wr2hi, *wr2lo, *hhi, *hlo, *mhi, *mlo, *o1hi, *o1lo;
    cudaGetSymbolAddress((void**)&h,      g_h);
    cudaGetSymbolAddress((void**)&invdeg, g_invdeg);
    cudaGetSymbolAddress((void**)&degi,   g_degi);
    cudaGetSymbolAddress((void**)&off,    g_off);
    cudaGetSymbolAddress((void**)&cur,    g_cur);
    cudaGetSymbolAddress((void**)&src,    g_src);
    cudaGetSymbolAddress((void**)&dst,    g_dst);
    cudaGetSymbolAddress((void**)&csr,    g_csr);
    cudaGetSymbolAddress((void**)&xhi,   g_xhi);   cudaGetSymbolAddress((void**)&xlo,   g_xlo);
    cudaGetSymbolAddress((void**)&w0hi,  g_w0hi);  cudaGetSymbolAddress((void**)&w0lo,  g_w0lo);
    cudaGetSymbolAddress((void**)&wl1hi, g_wl1hi); cudaGetSymbolAddress((void**)&wl1lo, g_wl1lo);
    cudaGetSymbolAddress((void**)&wr1hi, g_wr1hi); cudaGetSymbolAddress((void**)&wr1lo, g_wr1lo);
    cudaGetSymbolAddress((void**)&wl2hi, g_wl2hi); cudaGetSymbolAddress((void**)&wl2lo, g_wl2lo);
    cudaGetSymbolAddress((void**)&wr2hi, g_wr2hi); cudaGetSymbolAddress((void**)&wr2lo, g_wr2lo);
    cudaGetSymbolAddress((void**)&hhi,   g_hhi);   cudaGetSymbolAddress((void**)&hlo,   g_hlo);
    cudaGetSymbolAddress((void**)&mhi,   g_mhi);   cudaGetSymbolAddress((void**)&mlo,   g_mlo);
    cudaGetSymbolAddress((void**)&o1hi,  g_o1hi);  cudaGetSymbolAddress((void**)&o1lo,  g_o1lo);

    const int EB = (EE + 255) / 256;
    const int SPLIT_N = NN * DIN + DIN * DOUT + 4 * DOUT * DOUT;
    dim3 mgrid(DOUT / 64, (NN + 127) / 128);    // (4, 79)

    detect_kernel<<<1, 256>>>(ei);                                     // k1
    cudaMemsetAsync(degi, 0, NN * sizeof(int));
    decode_degi_kernel<<<EB, 256>>>(ei, src, dst, degi);               // k2
    split_kernel<<<(SPLIT_N + 255) / 256, 256>>>(x, W0, Wl1, Wr1, Wl2, Wr2);  // k3

    // gemm1: h = x @ W0 + b0  (bf16x3: 3 passes, K=512) — k4, capture target
    {
        PassList P{};
        P.A[0] = xhi; P.W[0] = w0hi;
        P.A[1] = xlo; P.W[1] = w0hi;
        P.A[2] = xhi; P.W[2] = w0lo;
        gemm_mma<DIN, 3, false, false, true><<<mgrid, 256>>>(
            P, b0, nullptr, h, hhi, hlo, NN);
    }

    scan_kernel<<<1, 256>>>(degi, off, cur, invdeg);                   // k5
    fill_kernel<<<EB, 256>>>(src, dst, cur, csr);                      // k6

    // conv1
    gather_kernel<<<NN, 64>>>(h, csr, off, degi, invdeg, mhi, mlo);
    {
        PassList P{};
        P.A[0] = mhi; P.W[0] = wl1hi;
        P.A[1] = mlo; P.W[1] = wl1hi;
        P.A[2] = mhi; P.W[2] = wl1lo;
        P.A[3] = hhi; P.W[3] = wr1hi;
        P.A[4] = hlo; P.W[4] = wr1hi;
        P.A[5] = hhi; P.W[5] = wr1lo;
        gemm_mma<DOUT, 6, true, true, true><<<mgrid, 256>>>(
            P, bl1, h, out1, o1hi, o1lo, NN);
    }

    // conv2
    gather_kernel<<<NN, 64>>>(out1, csr, off, degi, invdeg, mhi, mlo);
    {
        PassList P{};
        P.A[0] = mhi;  P.W[0] = wl2hi;
        P.A[1] = mlo;  P.W[1] = wl2hi;
        P.A[2] = mhi;  P.W[2] = wl2lo;
        P.A[3] = o1hi; P.W[3] = wr2hi;
        P.A[4] = o1lo; P.W[4] = wr2hi;
        P.A[5] = o1hi; P.W[5] = wr2lo;
        gemm_mma<DOUT, 6, false, true, false><<<mgrid, 256>>>(
            P, bl2, out1, out2, nullptr, nullptr, NN);
    }
}

// round 7
// speedup vs baseline: 2.0739x; 1.1056x over previous
#include <cuda_runtime.h>
#include <cuda_bf16.h>
#include <cstdint>
#include <cstddef>

constexpr int NN   = 10000;
constexpr int EE   = 320000;
constexpr int DIN  = 512;
constexpr int DOUT = 256;

// ---------------- scratch (__device__ globals; no allocs allowed) ----------
__device__ float g_h[(size_t)NN * DOUT];
__device__ float g_invdeg[NN];
__device__ int   g_degi[NN];
__device__ int   g_off[NN];
__device__ int   g_cur[NN];
__device__ int   g_src[EE];
__device__ int   g_dst[EE];
__device__ int   g_csr[EE];
__device__ int   g_is64;

// bf16 hi/lo split operands
__device__ __nv_bfloat16 g_xhi[(size_t)NN * DIN],  g_xlo[(size_t)NN * DIN];
__device__ __nv_bfloat16 g_w0hi[DIN * DOUT],       g_w0lo[DIN * DOUT];
__device__ __nv_bfloat16 g_wl1hi[DOUT * DOUT],     g_wl1lo[DOUT * DOUT];
__device__ __nv_bfloat16 g_wr1hi[DOUT * DOUT],     g_wr1lo[DOUT * DOUT];
__device__ __nv_bfloat16 g_wl2hi[DOUT * DOUT],     g_wl2lo[DOUT * DOUT];
__device__ __nv_bfloat16 g_wr2hi[DOUT * DOUT],     g_wr2lo[DOUT * DOUT];
__device__ __nv_bfloat16 g_hhi[(size_t)NN * DOUT], g_hlo[(size_t)NN * DOUT];
__device__ __nv_bfloat16 g_mhi[(size_t)NN * DOUT], g_mlo[(size_t)NN * DOUT];
__device__ __nv_bfloat16 g_o1hi[(size_t)NN * DOUT], g_o1lo[(size_t)NN * DOUT];

// ---------------------------------------------------------------------------
// Edge-index dtype detection (int64 vs int32).
// ---------------------------------------------------------------------------
__global__ void detect_kernel(const int* __restrict__ raw) {
    int nz = 0;
    for (int i = threadIdx.x; i < 1024; i += blockDim.x)
        nz |= (raw[2 * i + 1] != 0);
    nz = __syncthreads_or(nz);
    if (threadIdx.x == 0) g_is64 = nz ? 0 : 1;
}

// Decode edge_index into int32 src/dst + in-degree histogram.
__global__ void decode_degi_kernel(const int* __restrict__ raw,
                                   int* __restrict__ src, int* __restrict__ dst,
                                   int* __restrict__ degi) {
    int e = blockIdx.x * blockDim.x + threadIdx.x;
    if (e >= EE) return;
    int s, d;
    if (g_is64) { s = raw[2 * e]; d = raw[2 * (EE + e)]; }
    else        { s = raw[e];     d = raw[EE + e]; }
    src[e] = s;
    dst[e] = d;
    atomicAdd(&degi[d], 1);
}

// ---------------------------------------------------------------------------
// bf16 hi/lo split of x and the five weight matrices (one launch).
// ---------------------------------------------------------------------------
__global__ void split_kernel(const float* __restrict__ x,  const float* __restrict__ W0,
                             const float* __restrict__ Wl1, const float* __restrict__ Wr1,
                             const float* __restrict__ Wl2, const float* __restrict__ Wr2) {
    constexpr int S0 = NN * DIN;
    constexpr int S1 = DIN * DOUT;
    constexpr int S2 = DOUT * DOUT;
    int i = blockIdx.x * blockDim.x + threadIdx.x;
    const float* src; __nv_bfloat16 *hi, *lo; int off;
    if      (i < S0)               { src = x;   hi = g_xhi;  lo = g_xlo;  off = i; }
    else if (i < S0 + S1)          { src = W0;  hi = g_w0hi; lo = g_w0lo; off = i - S0; }
    else if (i < S0 + S1 + S2)     { src = Wl1; hi = g_wl1hi; lo = g_wl1lo; off = i - S0 - S1; }
    else if (i < S0 + S1 + 2 * S2) { src = Wr1; hi = g_wr1hi; lo = g_wr1lo; off = i - S0 - S1 - S2; }
    else if (i < S0 + S1 + 3 * S2) { src = Wl2; hi = g_wl2hi; lo = g_wl2lo; off = i - S0 - S1 - 2 * S2; }
    else if (i < S0 + S1 + 4 * S2) { src = Wr2; hi = g_wr2hi; lo = g_wr2lo; off = i - S0 - S1 - 3 * S2; }
    else return;
    float v = src[off];
    __nv_bfloat16 h = __float2bfloat16(v);
    hi[off] = h;
    lo[off] = __float2bfloat16(v - __bfloat162float(h));
}

// ---------------------------------------------------------------------------
// Exclusive scan over degrees -> CSR offsets + cursors + invdeg (1 block).
// ---------------------------------------------------------------------------
__global__ void scan_kernel(const int* __restrict__ degi, int* __restrict__ off,
                            int* __restrict__ cur, float* __restrict__ invdeg) {
    __shared__ int part[256];
    const int t = threadIdx.x;
    const int CH = (NN + 255) / 256;
    const int s0 = t * CH;
    int sum = 0;
    for (int j = 0; j < CH; j++) { int i = s0 + j; if (i < NN) sum += degi[i]; }
    part[t] = sum;
    __syncthreads();
    for (int d = 1; d < 256; d <<= 1) {
        int v = (t >= d) ? part[t - d] : 0;
        __syncthreads();
        part[t] += v;
        __syncthreads();
    }
    int run = (t > 0) ? part[t - 1] : 0;
    for (int j = 0; j < CH; j++) {
        int i = s0 + j;
        if (i < NN) {
            off[i] = run; cur[i] = run;
            int d = degi[i]; run += d;
            invdeg[i] = 1.0f / fmaxf((float)d, 1.0f);
        }
    }
}

__global__ void fill_kernel(const int* __restrict__ src, const int* __restrict__ dst,
                            int* __restrict__ cur, int* __restrict__ csr) {
    int e = blockIdx.x * blockDim.x + threadIdx.x;
    if (e < EE) {
        int p = atomicAdd(&cur[dst[e]], 1);
        csr[p] = src[e];
    }
}

// ---------------------------------------------------------------------------
// CSR gather: mean[i] = invdeg_i * sum h[src(e)], emitted as bf16 hi/lo.
// ---------------------------------------------------------------------------
__global__ void gather_kernel(const float* __restrict__ h,
                              const int* __restrict__ csr,
                              const int* __restrict__ off,
                              const int* __restrict__ degi,
                              const float* __restrict__ invdeg,
                              __nv_bfloat16* __restrict__ mhi,
                              __nv_bfloat16* __restrict__ mlo) {
    const int node = blockIdx.x;
    const int t = threadIdx.x;               // 0..63
    const int base = off[node];
    const int n = degi[node];
    const float4* hp = (const float4*)h;
    float4 acc = make_float4(0.f, 0.f, 0.f, 0.f);
    int e = 0;
    for (; e + 4 <= n; e += 4) {
        int s0 = csr[base + e + 0];
        int s1 = csr[base + e + 1];
        int s2 = csr[base + e + 2];
        int s3 = csr[base + e + 3];
        float4 v0 = hp[(size_t)s0 * 64 + t];
        float4 v1 = hp[(size_t)s1 * 64 + t];
        float4 v2 = hp[(size_t)s2 * 64 + t];
        float4 v3 = hp[(size_t)s3 * 64 + t];
        acc.x += (v0.x + v1.x) + (v2.x + v3.x);
        acc.y += (v0.y + v1.y) + (v2.y + v3.y);
        acc.z += (v0.z + v1.z) + (v2.z + v3.z);
        acc.w += (v0.w + v1.w) + (v2.w + v3.w);
    }
    for (; e < n; e++) {
        int s = csr[base + e];
        float4 v = hp[(size_t)s * 64 + t];
        acc.x += v.x; acc.y += v.y; acc.z += v.z; acc.w += v.w;
    }
    const float s = invdeg[node];
    float o[4] = {acc.x * s, acc.y * s, acc.z * s, acc.w * s};
    __nv_bfloat16 hi[4], lo[4];
#pragma unroll
    for (int j = 0; j < 4; j++) {
        hi[j] = __float2bfloat16(o[j]);
        lo[j] = __float2bfloat16(o[j] - __bfloat162float(hi[j]));
    }
    size_t p = (size_t)node * DOUT + t * 4;
    __nv_bfloat162 a, b;
    a.x = hi[0]; a.y = hi[1]; b.x = hi[2]; b.y = hi[3];
    *(__nv_bfloat162*)(mhi + p) = a; *(__nv_bfloat162*)(mhi + p + 2) = b;
    a.x = lo[0]; a.y = lo[1]; b.x = lo[2]; b.y = lo[3];
    *(__nv_bfloat162*)(mlo + p) = a; *(__nv_bfloat162*)(mlo + p + 2) = b;
}

// ---------------------------------------------------------------------------
// Tensor-core GEMM (bf16x3 split), cp.async 3-stage pipelined:
//   C = op( sum_p A_p @ W_p + bias ) [+ res], optional bf16 hi/lo re-split.
// Block 128x64, 8 warps (32x32 each), BK=32, mma.sync m16n8k16 bf16->f32.
// ---------------------------------------------------------------------------
struct PassList {
    const __nv_bfloat16* A[6];
    const __nv_bfloat16* W[6];
};

#define LDSM4(d0, d1, d2, d3, addr) \
    asm volatile("ldmatrix.sync.aligned.m8n8.x4.shared.b16 {%0,%1,%2,%3}, [%4];" \
        : "=r"(d0), "=r"(d1), "=r"(d2), "=r"(d3) : "r"(addr))
#define LDSM4T(d0, d1, d2, d3, addr) \
    asm volatile("ldmatrix.sync.aligned.m8n8.x4.trans.shared.b16 {%0,%1,%2,%3}, [%4];" \
        : "=r"(d0), "=r"(d1), "=r"(d2), "=r"(d3) : "r"(addr))
#define MMA16816(c, a, b0, b1) \
    asm volatile("mma.sync.aligned.m16n8k16.row.col.f32.bf16.bf16.f32 " \
        "{%0,%1,%2,%3}, {%4,%5,%6,%7}, {%8,%9}, {%0,%1,%2,%3};" \
        : "+f"(c[0]), "+f"(c[1]), "+f"(c[2]), "+f"(c[3]) \
        : "r"(a[0]), "r"(a[1]), "r"(a[2]), "r"(a[3]), "r"(b0), "r"(b1))
#define CPA16(dst, src, sz) \
    asm volatile("cp.async.cg.shared.global [%0], [%1], 16, %2;" \
        :: "r"(dst), "l"(src), "r"(sz))
#define CPA_COMMIT() asm volatile("cp.async.commit_group;")

constexpr int ASTR = 40;   // halfs; 80B row stride
constexpr int WSTR = 72;   // halfs; 144B row stride
constexpr int ABUF = 128 * ASTR;   // halfs per A stage buffer
constexpr int WBUF = 32 * WSTR;    // halfs per W stage buffer
constexpr int PIPE = 3;

template<int K, int NP, bool RELU, bool RES, bool OUTS>
__global__ __launch_bounds__(256)
void gemm_mma(PassList P, const float* __restrict__ bias, const float* __restrict__ res,
              float* __restrict__ C, __nv_bfloat16* __restrict__ Chi,
              __nv_bfloat16* __restrict__ Clo, int M) {
    constexpr int KS = K / 32;
    constexpr int NST = NP * KS;
    __shared__ __align__(16) __nv_bfloat16 As[PIPE * ABUF];
    __shared__ __align__(16) __nv_bfloat16 Ws[PIPE * WBUF];

    const int tid = threadIdx.x, wid = tid >> 5, lane = tid & 31;
    const int row0 = blockIdx.y * 128, col0 = blockIdx.x * 64;
    const int mb = (wid & 3) * 32, nb = (wid >> 2) * 32;

    float acc[2][4][4];
#pragma unroll
    for (int mt = 0; mt < 2; mt++)
#pragma unroll
        for (int nt = 0; nt < 4; nt++)
#pragma unroll
            for (int r = 0; r < 4; r++) acc[mt][nt][r] = 0.f;

    // cp.async load mapping: 2x 16B for A, 1x 16B for W per thread per stage
    const int arow = tid >> 2;            // 0..63 (and +64)
    const int achunk = (tid & 3) * 8;     // half offset within 32-wide K tile
    const int wk = tid >> 3;              // 0..31
    const int wn = (tid & 7) * 8;

    const uint32_t asu = (uint32_t)__cvta_generic_to_shared(As);
    const uint32_t wsu = (uint32_t)__cvta_generic_to_shared(Ws);

    const int r0g = row0 + arow, r1g = r0g + 64;
    const int sz0 = (r0g < M) ? 16 : 0, sz1 = (r1g < M) ? 16 : 0;
    const int r0c = (r0g < M) ? r0g : 0, r1c = (r1g < M) ? r1g : 0;

#define ISSUE(S, BUF) { \
        const int pass = (S) / KS; const int k0 = ((S) - pass * KS) * 32; \
        const __nv_bfloat16* Ap = P.A[pass]; const __nv_bfloat16* Wp = P.W[pass]; \
        CPA16(asu + ((BUF) * ABUF + arow * ASTR + achunk) * 2, \
              Ap + (size_t)r0c * K + k0 + achunk, sz0); \
        CPA16(asu + ((BUF) * ABUF + (arow + 64) * ASTR + achunk) * 2, \
              Ap + (size_t)r1c * K + k0 + achunk, sz1); \
        CPA16(wsu + ((BUF) * WBUF + wk * WSTR + wn) * 2, \
              Wp + (size_t)(k0 + wk) * DOUT + col0 + wn, 16); \
        CPA_COMMIT(); \
    }

    ISSUE(0, 0);
    ISSUE(1, 1);

    const int r = lane & 7, selr = lane >> 3;
    const uint32_t aoff = (uint32_t)((mb + (selr & 1) * 8 + r) * ASTR + (selr >> 1) * 8) * 2;
    const uint32_t boff = (uint32_t)(((selr & 1) * 8 + r) * WSTR + nb + (selr >> 1) * 8) * 2;

    for (int s = 0; s < NST; s++) {
        if (s + 1 < NST) { asm volatile("cp.async.wait_group 1;"); }
        else             { asm volatile("cp.async.wait_group 0;"); }
        __syncthreads();

        const int buf = s % PIPE;
        const uint32_t abase = asu + buf * ABUF * 2 + aoff;
        const uint32_t wbase = wsu + buf * WBUF * 2 + boff;
#pragma unroll
        for (int kk = 0; kk < 32; kk += 16) {
            uint32_t a[2][4], bt0[4], bt1[4];
            uint32_t aaddr = abase + kk * 2;
            LDSM4(a[0][0], a[0][1], a[0][2], a[0][3], aaddr);
            LDSM4(a[1][0], a[1][1], a[1][2], a[1][3], aaddr + 16 * ASTR * 2);
            uint32_t baddr = wbase + kk * WSTR * 2;
            LDSM4T(bt0[0], bt0[1], bt0[2], bt0[3], baddr);
            LDSM4T(bt1[0], bt1[1], bt1[2], bt1[3], baddr + 16 * 2);
#pragma unroll
            for (int mt = 0; mt < 2; mt++) {
                MMA16816(acc[mt][0], a[mt], bt0[0], bt0[1]);
                MMA16816(acc[mt][1], a[mt], bt0[2], bt0[3]);
                MMA16816(acc[mt][2], a[mt], bt1[0], bt1[1]);
                MMA16816(acc[mt][3], a[mt], bt1[2], bt1[3]);
            }
        }
        __syncthreads();
        if (s + 2 < NST) ISSUE(s + 2, (s + 2) % PIPE);
    }
#undef ISSUE

    // epilogue
    const int g = lane >> 2, tig = lane & 3;
#pragma unroll
    for (int mt = 0; mt < 2; mt++) {
#pragma unroll
        for (int half = 0; half < 2; half++) {
            const int row = row0 + mb + mt * 16 + g + half * 8;
            if (row >= M) continue;
#pragma unroll
            for (int nt = 0; nt < 4; nt++) {
                const int col = col0 + nb + nt * 8 + tig * 2;
                float v0 = acc[mt][nt][half * 2 + 0] + bias[col];
                float v1 = acc[mt][nt][half * 2 + 1] + bias[col + 1];
                if (RELU) { v0 = fmaxf(v0, 0.f); v1 = fmaxf(v1, 0.f); }
                if (RES) {
                    float2 rr = *(const float2*)(res + (size_t)row * DOUT + col);
                    v0 += rr.x; v1 += rr.y;
                }
                float2 o; o.x = v0; o.y = v1;
                *(float2*)(C + (size_t)row * DOUT + col) = o;
                if (OUTS) {
                    __nv_bfloat16 h0 = __float2bfloat16(v0), h1 = __float2bfloat16(v1);
                    __nv_bfloat162 hh; hh.x = h0; hh.y = h1;
                    *(__nv_bfloat162*)(Chi + (size_t)row * DOUT + col) = hh;
                    __nv_bfloat162 ll;
                    ll.x = __float2bfloat16(v0 - __bfloat162float(h0));
                    ll.y = __float2bfloat16(v1 - __bfloat162float(h1));
                    *(__nv_bfloat162*)(Clo + (size_t)row * DOUT + col) = ll;
                }
            }
        }
    }
}

// ---------------------------------------------------------------------------
// Launch: detect(1) decode(2) split(3) gemm1(4=capture) scan fill
//         gather gemm2 gather gemm3
// ---------------------------------------------------------------------------
extern "C" void kernel_launch(void* const* d_in, const int* in_sizes, int n_in,
                              void* d_out, int out_size) {
    const float* x   = (const float*)d_in[0];
    const int*   ei  = (const int*)d_in[1];
    const float* W0  = (const float*)d_in[2];
    const float* b0  = (const float*)d_in[3];
    const float* Wl1 = (const float*)d_in[4];
    const float* bl1 = (const float*)d_in[5];
    const float* Wr1 = (const float*)d_in[6];
    const float* Wl2 = (const float*)d_in[7];
    const float* bl2 = (const float*)d_in[8];
    const float* Wr2 = (const float*)d_in[9];

    float* out1 = (float*)d_out;
    float* out2 = out1 + (size_t)NN * DOUT;

    float *h, *invdeg;
    int *degi, *off, *cur, *src, *dst, *csr;
    __nv_bfloat16 *xhi, *xlo, *w0hi, *w0lo, *wl1hi, *wl1lo, *wr1hi, *wr1lo;
    __nv_bfloat16 *wl2hi, *wl2lo, *wr2hi, *wr2lo, *hhi, *hlo, *mhi, *mlo, *o1hi, *o1lo;
    cudaGetSymbolAddress((void**)&h,      g_h);
    cudaGetSymbolAddress((void**)&invdeg, g_invdeg);
    cudaGetSymbolAddress((void**)&degi,   g_degi);
    cudaGetSymbolAddress((void**)&off,    g_off);
    cudaGetSymbolAddress((void**)&cur,    g_cur);
    cudaGetSymbolAddress((void**)&src,    g_src);
    cudaGetSymbolAddress((void**)&dst,    g_dst);
    cudaGetSymbolAddress((void**)&csr,    g_csr);
    cudaGetSymbolAddress((void**)&xhi,   g_xhi);   cudaGetSymbolAddress((void**)&xlo,   g_xlo);
    cudaGetSymbolAddress((void**)&w0hi,  g_w0hi);  cudaGetSymbolAddress((void**)&w0lo,  g_w0lo);
    cudaGetSymbolAddress((void**)&wl1hi, g_wl1hi); cudaGetSymbolAddress((void**)&wl1lo, g_wl1lo);
    cudaGetSymbolAddress((void**)&wr1hi, g_wr1hi); cudaGetSymbolAddress((void**)&wr1lo, g_wr1lo);
    cudaGetSymbolAddress((void**)&wl2hi, g_wl2hi); cudaGetSymbolAddress((void**)&wl2lo, g_wl2lo);
    cudaGetSymbolAddress((void**)&wr2hi, g_wr2hi); cudaGetSymbolAddress((void**)&wr2lo, g_wr2lo);
    cudaGetSymbolAddress((void**)&hhi,   g_hhi);   cudaGetSymbolAddress((void**)&hlo,   g_hlo);
    cudaGetSymbolAddress((void**)&mhi,   g_mhi);   cudaGetSymbolAddress((void**)&mlo,   g_mlo);
    cudaGetSymbolAddress((void**)&o1hi,  g_o1hi);  cudaGetSymbolAddress((void**)&o1lo,  g_o1lo);

    const int EB = (EE + 255) / 256;
    const int SPLIT_N = NN * DIN + DIN * DOUT + 4 * DOUT * DOUT;
    dim3 mgrid(DOUT / 64, (NN + 127) / 128);    // (4, 79)

    detect_kernel<<<1, 256>>>(ei);                                     // k1
    cudaMemsetAsync(degi, 0, NN * sizeof(int));
    decode_degi_kernel<<<EB, 256>>>(ei, src, dst, degi);               // k2
    split_kernel<<<(SPLIT_N + 255) / 256, 256>>>(x, W0, Wl1, Wr1, Wl2, Wr2);  // k3

    // gemm1: h = x @ W0 + b0  (bf16x3: 3 passes, K=512) — k4, capture target
    {
        PassList P{};
        P.A[0] = xhi; P.W[0] = w0hi;
        P.A[1] = xlo; P.W[1] = w0hi;
        P.A[2] = xhi; P.W[2] = w0lo;
        gemm_mma<DIN, 3, false, false, true><<<mgrid, 256>>>(
            P, b0, nullptr, h, hhi, hlo, NN);
    }

    scan_kernel<<<1, 256>>>(degi, off, cur, invdeg);                   // k5
    fill_kernel<<<EB, 256>>>(src, dst, cur, csr);                      // k6

    // conv1
    gather_kernel<<<NN, 64>>>(h, csr, off, degi, invdeg, mhi, mlo);
    {
        PassList P{};
        P.A[0] = mhi; P.W[0] = wl1hi;
        P.A[1] = mlo; P.W[1] = wl1hi;
        P.A[2] = mhi; P.W[2] = wl1lo;
        P.A[3] = hhi; P.W[3] = wr1hi;
        P.A[4] = hlo; P.W[4] = wr1hi;
        P.A[5] = hhi; P.W[5] = wr1lo;
        gemm_mma<DOUT, 6, true, true, true><<<mgrid, 256>>>(
            P, bl1, h, out1, o1hi, o1lo, NN);
    }

    // conv2
    gather_kernel<<<NN, 64>>>(out1, csr, off, degi, invdeg, mhi, mlo);
    {
        PassList P{};
        P.A[0] = mhi;  P.W[0] = wl2hi;
        P.A[1] = mlo;  P.W[1] = wl2hi;
        P.A[2] = mhi;  P.W[2] = wl2lo;
        P.A[3] = o1hi; P.W[3] = wr2hi;
        P.A[4] = o1lo; P.W[4] = wr2hi;
        P.A[5] = o1hi; P.W[5] = wr2lo;
        gemm_mma<DOUT, 6, false, true, false><<<mgrid, 256>>>(
            P, bl2, out1, out2, nullptr, nullptr, NN);
    }
}

// round 8
// speedup vs baseline: 2.1870x; 1.0545x over previous
#include <cuda_runtime.h>
#include <cuda_bf16.h>
#include <cstdint>
#include <cstddef>

constexpr int NN   = 10000;
constexpr int EE   = 320000;
constexpr int DIN  = 512;
constexpr int DOUT = 256;

// ---------------- scratch (__device__ globals; no allocs allowed) ----------
__device__ float g_h[(size_t)NN * DOUT];
__device__ float g_invdeg[NN];
__device__ int   g_degi[NN];
__device__ int   g_off[NN];
__device__ int   g_cur[NN];
__device__ int   g_src[EE];
__device__ int   g_dst[EE];
__device__ int   g_csr[EE];
__device__ int   g_is64;

// bf16 hi/lo split operands
__device__ __nv_bfloat16 g_xhi[(size_t)NN * DIN],  g_xlo[(size_t)NN * DIN];
__device__ __nv_bfloat16 g_w0hi[DIN * DOUT],       g_w0lo[DIN * DOUT];
__device__ __nv_bfloat16 g_wl1hi[DOUT * DOUT],     g_wl1lo[DOUT * DOUT];
__device__ __nv_bfloat16 g_wr1hi[DOUT * DOUT],     g_wr1lo[DOUT * DOUT];
__device__ __nv_bfloat16 g_wl2hi[DOUT * DOUT],     g_wl2lo[DOUT * DOUT];
__device__ __nv_bfloat16 g_wr2hi[DOUT * DOUT],     g_wr2lo[DOUT * DOUT];
__device__ __nv_bfloat16 g_hhi[(size_t)NN * DOUT], g_hlo[(size_t)NN * DOUT];
__device__ __nv_bfloat16 g_mhi[(size_t)NN * DOUT], g_mlo[(size_t)NN * DOUT];
__device__ __nv_bfloat16 g_o1hi[(size_t)NN * DOUT], g_o1lo[(size_t)NN * DOUT];

// ---------------------------------------------------------------------------
// Edge-index dtype detection (int64 vs int32).
// ---------------------------------------------------------------------------
__global__ void detect_kernel(const int* __restrict__ raw) {
    int nz = 0;
    for (int i = threadIdx.x; i < 1024; i += blockDim.x)
        nz |= (raw[2 * i + 1] != 0);
    nz = __syncthreads_or(nz);
    if (threadIdx.x == 0) g_is64 = nz ? 0 : 1;
}

// Decode edge_index into int32 src/dst + in-degree histogram.
__global__ void decode_degi_kernel(const int* __restrict__ raw,
                                   int* __restrict__ src, int* __restrict__ dst,
                                   int* __restrict__ degi) {
    int e = blockIdx.x * blockDim.x + threadIdx.x;
    if (e >= EE) return;
    int s, d;
    if (g_is64) { s = raw[2 * e]; d = raw[2 * (EE + e)]; }
    else        { s = raw[e];     d = raw[EE + e]; }
    src[e] = s;
    dst[e] = d;
    atomicAdd(&degi[d], 1);
}

// ---------------------------------------------------------------------------
// bf16 hi/lo split of x and the five weight matrices (one launch).
// ---------------------------------------------------------------------------
__global__ void split_kernel(const float* __restrict__ x,  const float* __restrict__ W0,
                             const float* __restrict__ Wl1, const float* __restrict__ Wr1,
                             const float* __restrict__ Wl2, const float* __restrict__ Wr2) {
    constexpr int S0 = NN * DIN;
    constexpr int S1 = DIN * DOUT;
    constexpr int S2 = DOUT * DOUT;
    int i = blockIdx.x * blockDim.x + threadIdx.x;
    const float* src; __nv_bfloat16 *hi, *lo; int off;
    if      (i < S0)               { src = x;   hi = g_xhi;  lo = g_xlo;  off = i; }
    else if (i < S0 + S1)          { src = W0;  hi = g_w0hi; lo = g_w0lo; off = i - S0; }
    else if (i < S0 + S1 + S2)     { src = Wl1; hi = g_wl1hi; lo = g_wl1lo; off = i - S0 - S1; }
    else if (i < S0 + S1 + 2 * S2) { src = Wr1; hi = g_wr1hi; lo = g_wr1lo; off = i - S0 - S1 - S2; }
    else if (i < S0 + S1 + 3 * S2) { src = Wl2; hi = g_wl2hi; lo = g_wl2lo; off = i - S0 - S1 - 2 * S2; }
    else if (i < S0 + S1 + 4 * S2) { src = Wr2; hi = g_wr2hi; lo = g_wr2lo; off = i - S0 - S1 - 3 * S2; }
    else return;
    float v = src[off];
    __nv_bfloat16 h = __float2bfloat16(v);
    hi[off] = h;
    lo[off] = __float2bfloat16(v - __bfloat162float(h));
}

// ---------------------------------------------------------------------------
// Exclusive scan over degrees -> CSR offsets + cursors + invdeg (1 block).
// ---------------------------------------------------------------------------
__global__ void scan_kernel(const int* __restrict__ degi, int* __restrict__ off,
                            int* __restrict__ cur, float* __restrict__ invdeg) {
    __shared__ int part[256];
    const int t = threadIdx.x;
    const int CH = (NN + 255) / 256;
    const int s0 = t * CH;
    int sum = 0;
    for (int j = 0; j < CH; j++) { int i = s0 + j; if (i < NN) sum += degi[i]; }
    part[t] = sum;
    __syncthreads();
    for (int d = 1; d < 256; d <<= 1) {
        int v = (t >= d) ? part[t - d] : 0;
        __syncthreads();
        part[t] += v;
        __syncthreads();
    }
    int run = (t > 0) ? part[t - 1] : 0;
    for (int j = 0; j < CH; j++) {
        int i = s0 + j;
        if (i < NN) {
            off[i] = run; cur[i] = run;
            int d = degi[i]; run += d;
            invdeg[i] = 1.0f / fmaxf((float)d, 1.0f);
        }
    }
}

__global__ void fill_kernel(const int* __restrict__ src, const int* __restrict__ dst,
                            int* __restrict__ cur, int* __restrict__ csr) {
    int e = blockIdx.x * blockDim.x + threadIdx.x;
    if (e < EE) {
        int p = atomicAdd(&cur[dst[e]], 1);
        csr[p] = src[e];
    }
}

// ---------------------------------------------------------------------------
// CSR gather: mean[i] = invdeg_i * sum h[src(e)], emitted as bf16 hi/lo.
// ---------------------------------------------------------------------------
__global__ void gather_kernel(const float* __restrict__ h,
                              const int* __restrict__ csr,
                              const int* __restrict__ off,
                              const int* __restrict__ degi,
                              const float* __restrict__ invdeg,
                              __nv_bfloat16* __restrict__ mhi,
                              __nv_bfloat16* __restrict__ mlo) {
    const int node = blockIdx.x;
    const int t = threadIdx.x;               // 0..63
    const int base = off[node];
    const int n = degi[node];
    const float4* hp = (const float4*)h;
    float4 acc = make_float4(0.f, 0.f, 0.f, 0.f);
    int e = 0;
    for (; e + 4 <= n; e += 4) {
        int s0 = csr[base + e + 0];
        int s1 = csr[base + e + 1];
        int s2 = csr[base + e + 2];
        int s3 = csr[base + e + 3];
        float4 v0 = hp[(size_t)s0 * 64 + t];
        float4 v1 = hp[(size_t)s1 * 64 + t];
        float4 v2 = hp[(size_t)s2 * 64 + t];
        float4 v3 = hp[(size_t)s3 * 64 + t];
        acc.x += (v0.x + v1.x) + (v2.x + v3.x);
        acc.y += (v0.y + v1.y) + (v2.y + v3.y);
        acc.z += (v0.z + v1.z) + (v2.z + v3.z);
        acc.w += (v0.w + v1.w) + (v2.w + v3.w);
    }
    for (; e < n; e++) {
        int s = csr[base + e];
        float4 v = hp[(size_t)s * 64 + t];
        acc.x += v.x; acc.y += v.y; acc.z += v.z; acc.w += v.w;
    }
    const float s = invdeg[node];
    float o[4] = {acc.x * s, acc.y * s, acc.z * s, acc.w * s};
    __nv_bfloat16 hi[4], lo[4];
#pragma unroll
    for (int j = 0; j < 4; j++) {
        hi[j] = __float2bfloat16(o[j]);
        lo[j] = __float2bfloat16(o[j] - __bfloat162float(hi[j]));
    }
    size_t p = (size_t)node * DOUT + t * 4;
    __nv_bfloat162 a, b;
    a.x = hi[0]; a.y = hi[1]; b.x = hi[2]; b.y = hi[3];
    *(__nv_bfloat162*)(mhi + p) = a; *(__nv_bfloat162*)(mhi + p + 2) = b;
    a.x = lo[0]; a.y = lo[1]; b.x = lo[2]; b.y = lo[3];
    *(__nv_bfloat162*)(mlo + p) = a; *(__nv_bfloat162*)(mlo + p + 2) = b;
}

// ---------------------------------------------------------------------------
// Tensor-core GEMM (bf16x3 split), cp.async 3-stage pipelined.
// Block 64x64, 4 warps (32x32 warp tile), BK=32 -> grid 628 (4+ blocks/SM).
// Single __syncthreads per stage (PIPE=3 ring makes issue-after-wait safe).
// ---------------------------------------------------------------------------
struct PassList {
    const __nv_bfloat16* A[6];
    const __nv_bfloat16* W[6];
};

#define LDSM4(d0, d1, d2, d3, addr) \
    asm volatile("ldmatrix.sync.aligned.m8n8.x4.shared.b16 {%0,%1,%2,%3}, [%4];" \
        : "=r"(d0), "=r"(d1), "=r"(d2), "=r"(d3) : "r"(addr))
#define LDSM4T(d0, d1, d2, d3, addr) \
    asm volatile("ldmatrix.sync.aligned.m8n8.x4.trans.shared.b16 {%0,%1,%2,%3}, [%4];" \
        : "=r"(d0), "=r"(d1), "=r"(d2), "=r"(d3) : "r"(addr))
#define MMA16816(c, a, b0, b1) \
    asm volatile("mma.sync.aligned.m16n8k16.row.col.f32.bf16.bf16.f32 " \
        "{%0,%1,%2,%3}, {%4,%5,%6,%7}, {%8,%9}, {%0,%1,%2,%3};" \
        : "+f"(c[0]), "+f"(c[1]), "+f"(c[2]), "+f"(c[3]) \
        : "r"(a[0]), "r"(a[1]), "r"(a[2]), "r"(a[3]), "r"(b0), "r"(b1))
#define CPA16(dst, src, sz) \
    asm volatile("cp.async.cg.shared.global [%0], [%1], 16, %2;" \
        :: "r"(dst), "l"(src), "r"(sz))
#define CPA_COMMIT() asm volatile("cp.async.commit_group;")

constexpr int ASTR = 40;          // halfs; 80B row stride
constexpr int WSTR = 72;          // halfs; 144B row stride
constexpr int ABUF = 64 * ASTR;   // halfs per A stage buffer (64 rows x 32 k)
constexpr int WBUF = 32 * WSTR;   // halfs per W stage buffer (32 k x 64 n)
constexpr int PIPE = 3;

template<int K, int NP, bool RELU, bool RES, bool OUTS>
__global__ __launch_bounds__(128)
void gemm_mma(PassList P, const float* __restrict__ bias, const float* __restrict__ res,
              float* __restrict__ C, __nv_bfloat16* __restrict__ Chi,
              __nv_bfloat16* __restrict__ Clo, int M) {
    constexpr int KS = K / 32;
    constexpr int NST = NP * KS;
    __shared__ __align__(16) __nv_bfloat16 As[PIPE * ABUF];
    __shared__ __align__(16) __nv_bfloat16 Ws[PIPE * WBUF];

    const int tid = threadIdx.x, wid = tid >> 5, lane = tid & 31;
    const int row0 = blockIdx.y * 64, col0 = blockIdx.x * 64;
    const int mb = (wid & 1) * 32, nb = (wid >> 1) * 32;

    float acc[2][4][4];
#pragma unroll
    for (int mt = 0; mt < 2; mt++)
#pragma unroll
        for (int nt = 0; nt < 4; nt++)
#pragma unroll
            for (int r = 0; r < 4; r++) acc[mt][nt][r] = 0.f;

    // cp.async mapping (128 threads): A = 64 rows x 32 halfs -> 2 chunks/thr;
    // W = 32 rows x 64 halfs -> 2 chunks/thr.
    const int arow = tid >> 2;            // 0..31 (and +32)
    const int achunk = (tid & 3) * 8;     // half offset within 32-wide K tile
    const int wk = tid >> 2;              // 0..31
    const int wn = (tid & 3) * 16;        // two 16B chunks: wn, wn+8

    const uint32_t asu = (uint32_t)__cvta_generic_to_shared(As);
    const uint32_t wsu = (uint32_t)__cvta_generic_to_shared(Ws);

    const int r0g = row0 + arow, r1g = r0g + 32;
    const int sz0 = (r0g < M) ? 16 : 0, sz1 = (r1g < M) ? 16 : 0;
    const int r0c = (r0g < M) ? r0g : 0, r1c = (r1g < M) ? r1g : 0;

#define ISSUE(S, BUF) { \
        const int pass = (S) / KS; const int k0 = ((S) - pass * KS) * 32; \
        const __nv_bfloat16* Ap = P.A[pass]; const __nv_bfloat16* Wp = P.W[pass]; \
        CPA16(asu + ((BUF) * ABUF + arow * ASTR + achunk) * 2, \
              Ap + (size_t)r0c * K + k0 + achunk, sz0); \
        CPA16(asu + ((BUF) * ABUF + (arow + 32) * ASTR + achunk) * 2, \
              Ap + (size_t)r1c * K + k0 + achunk, sz1); \
        CPA16(wsu + ((BUF) * WBUF + wk * WSTR + wn) * 2, \
              Wp + (size_t)(k0 + wk) * DOUT + col0 + wn, 16); \
        CPA16(wsu + ((BUF) * WBUF + wk * WSTR + wn + 8) * 2, \
              Wp + (size_t)(k0 + wk) * DOUT + col0 + wn + 8, 16); \
        CPA_COMMIT(); \
    }

    ISSUE(0, 0);
    ISSUE(1, 1);

    const int r = lane & 7, selr = lane >> 3;
    const uint32_t aoff = (uint32_t)((mb + (selr & 1) * 8 + r) * ASTR + (selr >> 1) * 8) * 2;
    const uint32_t boff = (uint32_t)(((selr & 1) * 8 + r) * WSTR + nb + (selr >> 1) * 8) * 2;

    for (int s = 0; s < NST; s++) {
        if (s + 1 < NST) { asm volatile("cp.async.wait_group 1;"); }
        else             { asm volatile("cp.async.wait_group 0;"); }
        __syncthreads();
        // Safe: buffer (s+2)%3 == (s-1)%3, whose readers all passed this barrier.
        if (s + 2 < NST) ISSUE(s + 2, (s + 2) % PIPE);

        const int buf = s % PIPE;
        const uint32_t abase = asu + buf * ABUF * 2 + aoff;
        const uint32_t wbase = wsu + buf * WBUF * 2 + boff;
#pragma unroll
        for (int kk = 0; kk < 32; kk += 16) {
            uint32_t a[2][4], bt0[4], bt1[4];
            uint32_t aaddr = abase + kk * 2;
            LDSM4(a[0][0], a[0][1], a[0][2], a[0][3], aaddr);
            LDSM4(a[1][0], a[1][1], a[1][2], a[1][3], aaddr + 16 * ASTR * 2);
            uint32_t baddr = wbase + kk * WSTR * 2;
            LDSM4T(bt0[0], bt0[1], bt0[2], bt0[3], baddr);
            LDSM4T(bt1[0], bt1[1], bt1[2], bt1[3], baddr + 16 * 2);
#pragma unroll
            for (int mt = 0; mt < 2; mt++) {
                MMA16816(acc[mt][0], a[mt], bt0[0], bt0[1]);
                MMA16816(acc[mt][1], a[mt], bt0[2], bt0[3]);
                MMA16816(acc[mt][2], a[mt], bt1[0], bt1[1]);
                MMA16816(acc[mt][3], a[mt], bt1[2], bt1[3]);
            }
        }
    }
#undef ISSUE

    // epilogue
    const int g = lane >> 2, tig = lane & 3;
#pragma unroll
    for (int mt = 0; mt < 2; mt++) {
#pragma unroll
        for (int half = 0; half < 2; half++) {
            const int row = row0 + mb + mt * 16 + g + half * 8;
            if (row >= M) continue;
#pragma unroll
            for (int nt = 0; nt < 4; nt++) {
                const int col = col0 + nb + nt * 8 + tig * 2;
                float v0 = acc[mt][nt][half * 2 + 0] + bias[col];
                float v1 = acc[mt][nt][half * 2 + 1] + bias[col + 1];
                if (RELU) { v0 = fmaxf(v0, 0.f); v1 = fmaxf(v1, 0.f); }
                if (RES) {
                    float2 rr = *(const float2*)(res + (size_t)row * DOUT + col);
                    v0 += rr.x; v1 += rr.y;
                }
                float2 o; o.x = v0; o.y = v1;
                *(float2*)(C + (size_t)row * DOUT + col) = o;
                if (OUTS) {
                    __nv_bfloat16 h0 = __float2bfloat16(v0), h1 = __float2bfloat16(v1);
                    __nv_bfloat162 hh; hh.x = h0; hh.y = h1;
                    *(__nv_bfloat162*)(Chi + (size_t)row * DOUT + col) = hh;
                    __nv_bfloat162 ll;
                    ll.x = __float2bfloat16(v0 - __bfloat162float(h0));
                    ll.y = __float2bfloat16(v1 - __bfloat162float(h1));
                    *(__nv_bfloat162*)(Clo + (size_t)row * DOUT + col) = ll;
                }
            }
        }
    }
}

// ---------------------------------------------------------------------------
// Launch: detect(1) decode(2) split(3) gemm1(4=capture) scan fill
//         gather gemm2 gather gemm3
// ---------------------------------------------------------------------------
extern "C" void kernel_launch(void* const* d_in, const int* in_sizes, int n_in,
                              void* d_out, int out_size) {
    const float* x   = (const float*)d_in[0];
    const int*   ei  = (const int*)d_in[1];
    const float* W0  = (const float*)d_in[2];
    const float* b0  = (const float*)d_in[3];
    const float* Wl1 = (const float*)d_in[4];
    const float* bl1 = (const float*)d_in[5];
    const float* Wr1 = (const float*)d_in[6];
    const float* Wl2 = (const float*)d_in[7];
    const float* bl2 = (const float*)d_in[8];
    const float* Wr2 = (const float*)d_in[9];

    float* out1 = (float*)d_out;
    float* out2 = out1 + (size_t)NN * DOUT;

    float *h, *invdeg;
    int *degi, *off, *cur, *src, *dst, *csr;
    __nv_bfloat16 *xhi, *xlo, *w0hi, *w0lo, *wl1hi, *wl1lo, *wr1hi, *wr1lo;
    __nv_bfloat16 *wl2hi, *wl2lo, *wr2hi, *wr2lo, *hhi, *hlo, *mhi, *mlo, *o1hi, *o1lo;
    cudaGetSymbolAddress((void**)&h,      g_h);
    cudaGetSymbolAddress((void**)&invdeg, g_invdeg);
    cudaGetSymbolAddress((void**)&degi,   g_degi);
    cudaGetSymbolAddress((void**)&off,    g_off);
    cudaGetSymbolAddress((void**)&cur,    g_cur);
    cudaGetSymbolAddress((void**)&src,    g_src);
    cudaGetSymbolAddress((void**)&dst,    g_dst);
    cudaGetSymbolAddress((void**)&csr,    g_csr);
    cudaGetSymbolAddress((void**)&xhi,   g_xhi);   cudaGetSymbolAddress((void**)&xlo,   g_xlo);
    cudaGetSymbolAddress((void**)&w0hi,  g_w0hi);  cudaGetSymbolAddress((void**)&w0lo,  g_w0lo);
    cudaGetSymbolAddress((void**)&wl1hi, g_wl1hi); cudaGetSymbolAddress((void**)&wl1lo, g_wl1lo);
    cudaGetSymbolAddress((void**)&wr1hi, g_wr1hi); cudaGetSymbolAddress((void**)&wr1lo, g_wr1lo);
    cudaGetSymbolAddress((void**)&wl2hi, g_wl2hi); cudaGetSymbolAddress((void**)&wl2lo, g_wl2lo);
    cudaGetSymbolAddress((void**)&wr2hi, g_wr2hi); cudaGetSymbolAddress((void**)&wr2lo, g_wr2lo);
    cudaGetSymbolAddress((void**)&hhi,   g_hhi);   cudaGetSymbolAddress((void**)&hlo,   g_hlo);
    cudaGetSymbolAddress((void**)&mhi,   g_mhi);   cudaGetSymbolAddress((void**)&mlo,   g_mlo);
    cudaGetSymbolAddress((void**)&o1hi,  g_o1hi);  cudaGetSymbolAddress((void**)&o1lo,  g_o1lo);

    const int EB = (EE + 255) / 256;
    const int SPLIT_N = NN * DIN + DIN * DOUT + 4 * DOUT * DOUT;
    dim3 mgrid(DOUT / 64, (NN + 63) / 64);    // (4, 157) = 628 blocks

    detect_kernel<<<1, 256>>>(ei);                                     // k1
    cudaMemsetAsync(degi, 0, NN * sizeof(int));
    decode_degi_kernel<<<EB, 256>>>(ei, src, dst, degi);               // k2
    split_kernel<<<(SPLIT_N + 255) / 256, 256>>>(x, W0, Wl1, Wr1, Wl2, Wr2);  // k3

    // gemm1: h = x @ W0 + b0  (bf16x3: 3 passes, K=512) — k4, capture target
    {
        PassList P{};
        P.A[0] = xhi; P.W[0] = w0hi;
        P.A[1] = xlo; P.W[1] = w0hi;
        P.A[2] = xhi; P.W[2] = w0lo;
        gemm_mma<DIN, 3, false, false, true><<<mgrid, 128>>>(
            P, b0, nullptr, h, hhi, hlo, NN);
    }

    scan_kernel<<<1, 256>>>(degi, off, cur, invdeg);                   // k5
    fill_kernel<<<EB, 256>>>(src, dst, cur, csr);                      // k6

    // conv1
    gather_kernel<<<NN, 64>>>(h, csr, off, degi, invdeg, mhi, mlo);
    {
        PassList P{};
        P.A[0] = mhi; P.W[0] = wl1hi;
        P.A[1] = mlo; P.W[1] = wl1hi;
        P.A[2] = mhi; P.W[2] = wl1lo;
        P.A[3] = hhi; P.W[3] = wr1hi;
        P.A[4] = hlo; P.W[4] = wr1hi;
        P.A[5] = hhi; P.W[5] = wr1lo;
        gemm_mma<DOUT, 6, true, true, true><<<mgrid, 128>>>(
            P, bl1, h, out1, o1hi, o1lo, NN);
    }

    // conv2
    gather_kernel<<<NN, 64>>>(out1, csr, off, degi, invdeg, mhi, mlo);
    {
        PassList P{};
        P.A[0] = mhi;  P.W[0] = wl2hi;
        P.A[1] = mlo;  P.W[1] = wl2hi;
        P.A[2] = mhi;  P.W[2] = wl2lo;
        P.A[3] = o1hi; P.W[3] = wr2hi;
        P.A[4] = o1lo; P.W[4] = wr2hi;
        P.A[5] = o1hi; P.W[5] = wr2lo;
        gemm_mma<DOUT, 6, false, true, false><<<mgrid, 128>>>(
            P, bl2, out1, out2, nullptr, nullptr, NN);
    }
}